// round 1
// baseline (speedup 1.0000x reference)
#include <cuda_runtime.h>

// Problem constants
#define Bn      4
#define Tn      2048
#define Dn      768
#define Hn      12
#define HDn     64
#define MAXREL  128
#define Mrows   (Bn * Tn)   // 8192

// ---------------------------------------------------------------------------
// Scratch (alloc-free: __device__ globals)
// ---------------------------------------------------------------------------
__device__ __align__(16) float g_q[Mrows * Dn];
__device__ __align__(16) float g_k[Mrows * Dn];
__device__ __align__(16) float g_v[Mrows * Dn];
__device__ __align__(16) float g_ctx[Mrows * Dn];
__device__ float g_bias[2 * MAXREL + 1];

// ---------------------------------------------------------------------------
// Kernel 1: head-average of bias_table  -> g_bias[257]
// bias_table layout: [2*MAXREL+1, H] row-major
// ---------------------------------------------------------------------------
__global__ void bias_avg_kernel(const float* __restrict__ bt) {
    int i = threadIdx.x;
    if (i < 2 * MAXREL + 1) {
        float s = 0.f;
#pragma unroll
        for (int h = 0; h < Hn; h++) s += bt[i * Hn + h];
        g_bias[i] = s * (1.0f / Hn);
    }
}

// ---------------------------------------------------------------------------
// Kernel 2: SGEMM  C[M,N] = A[M,K] @ W[N,K]^T + bias[N]
// 128x128 block tile, BK=16, 256 threads, 8x8 register micro-tile
// ---------------------------------------------------------------------------
#define GBM 128
#define GBN 128
#define GBK 16

__global__ __launch_bounds__(256) void sgemm_nt(
    const float* __restrict__ A, const float* __restrict__ W,
    const float* __restrict__ bias, float* __restrict__ C,
    int M, int N, int K)
{
    __shared__ __align__(16) float As[GBK][GBM + 4];
    __shared__ __align__(16) float Bs[GBK][GBN + 4];

    const int t  = threadIdx.x;
    const int tx = t & 15;    // col group
    const int ty = t >> 4;    // row group
    const int m0 = blockIdx.x * GBM;
    const int n0 = blockIdx.y * GBN;

    float acc[8][8];
#pragma unroll
    for (int i = 0; i < 8; i++)
#pragma unroll
        for (int j = 0; j < 8; j++) acc[i][j] = 0.f;

    for (int k0 = 0; k0 < K; k0 += GBK) {
        // Load 128x16 tiles of A and W, store transposed (k-major in smem)
#pragma unroll
        for (int u = 0; u < 2; u++) {
            int g   = t * 2 + u;       // 0..511 float4 slots
            int row = g >> 2;          // 0..127
            int c4  = (g & 3) * 4;     // 0,4,8,12
            float4 va = *(const float4*)(A + (size_t)(m0 + row) * K + k0 + c4);
            As[c4 + 0][row] = va.x; As[c4 + 1][row] = va.y;
            As[c4 + 2][row] = va.z; As[c4 + 3][row] = va.w;
            float4 vb = *(const float4*)(W + (size_t)(n0 + row) * K + k0 + c4);
            Bs[c4 + 0][row] = vb.x; Bs[c4 + 1][row] = vb.y;
            Bs[c4 + 2][row] = vb.z; Bs[c4 + 3][row] = vb.w;
        }
        __syncthreads();
#pragma unroll
        for (int kk = 0; kk < GBK; kk++) {
            float a[8], b[8];
            *(float4*)&a[0] = *(const float4*)&As[kk][ty * 8];
            *(float4*)&a[4] = *(const float4*)&As[kk][ty * 8 + 4];
            *(float4*)&b[0] = *(const float4*)&Bs[kk][tx * 8];
            *(float4*)&b[4] = *(const float4*)&Bs[kk][tx * 8 + 4];
#pragma unroll
            for (int i = 0; i < 8; i++)
#pragma unroll
                for (int j = 0; j < 8; j++)
                    acc[i][j] += a[i] * b[j];
        }
        __syncthreads();
    }

    // Epilogue: add bias, write out (dims are exact multiples: no guards)
#pragma unroll
    for (int i = 0; i < 8; i++) {
        int mi = m0 + ty * 8 + i;
#pragma unroll
        for (int j = 0; j < 8; j += 4) {
            int nj = n0 + tx * 8 + j;
            float4 o;
            o.x = acc[i][j + 0] + bias[nj + 0];
            o.y = acc[i][j + 1] + bias[nj + 1];
            o.z = acc[i][j + 2] + bias[nj + 2];
            o.w = acc[i][j + 3] + bias[nj + 3];
            *(float4*)(C + (size_t)mi * N + nj) = o;
        }
    }
}

// ---------------------------------------------------------------------------
// Kernel 3: flash attention (fp32), per (q-tile of 128, head, batch)
// 256 threads: thread = 8 q-rows x 4 cols micro-tile
// Online softmax with relative-position bias from g_bias.
// ---------------------------------------------------------------------------
#define ABQ  128
#define ABK  64
#define QPAD (ABQ + 4)   // 132
#define KPAD (ABK + 4)   // 68

// smem floats: Qs 64*132 + Ks 64*68 + Vs 64*68 + Ps 64*132 + bias 260
#define ATTN_SMEM_FLOATS (64 * QPAD + 64 * KPAD + 64 * KPAD + 64 * QPAD + 260)

__global__ __launch_bounds__(256) void attn_kernel(
    const float* __restrict__ Q, const float* __restrict__ Kp,
    const float* __restrict__ Vp, float* __restrict__ Ctx)
{
    extern __shared__ __align__(16) float sm[];
    float* Qs  = sm;                       // [64][QPAD]  (d-major, transposed)
    float* Ks  = Qs + 64 * QPAD;           // [64][KPAD]  (d-major, transposed)
    float* Vs  = Ks + 64 * KPAD;           // [64][KPAD]  (key-major, natural)
    float* Ps  = Vs + 64 * KPAD;           // [64][QPAD]  (key-major, transposed)
    float* Bsm = Ps + 64 * QPAD;           // [257]

    const int t  = threadIdx.x;
    const int tx = t & 15;    // col group: 4 cols
    const int ty = t >> 4;    // row group: 8 rows
    const int q0 = blockIdx.x * ABQ;
    const int h  = blockIdx.y;
    const int b  = blockIdx.z;

    for (int i = t; i < 2 * MAXREL + 1; i += 256) Bsm[i] = g_bias[i];

    // Load Q tile [128 rows][64 d], store transposed Qs[d][row]
    const float* qbase = Q + ((size_t)(b * Tn + q0)) * Dn + h * HDn;
#pragma unroll
    for (int u = 0; u < 8; u++) {
        int g   = t * 8 + u;      // 0..2047 float4 slots
        int row = g >> 4;         // 0..127
        int d   = (g & 15) * 4;   // 0..60
        float4 v = *(const float4*)(qbase + (size_t)row * Dn + d);
        Qs[(d + 0) * QPAD + row] = v.x;
        Qs[(d + 1) * QPAD + row] = v.y;
        Qs[(d + 2) * QPAD + row] = v.z;
        Qs[(d + 3) * QPAD + row] = v.w;
    }

    float m_i[8], l_i[8], acc_o[8][4];
#pragma unroll
    for (int i = 0; i < 8; i++) {
        m_i[i] = -1e30f; l_i[i] = 0.f;
#pragma unroll
        for (int j = 0; j < 4; j++) acc_o[i][j] = 0.f;
    }

    const float scale = 0.125f;  // 1/sqrt(64)

    for (int kt = 0; kt < Tn; kt += ABK) {
        __syncthreads();  // prior Ps/Vs consumers done (also covers Q load, iter 0)

        // Load K (transposed) and V (natural) tiles: 64 rows x 64 d
        const float* kbase = Kp + ((size_t)(b * Tn + kt)) * Dn + h * HDn;
        const float* vbase = Vp + ((size_t)(b * Tn + kt)) * Dn + h * HDn;
#pragma unroll
        for (int u = 0; u < 4; u++) {
            int g   = t * 4 + u;      // 0..1023 float4 slots
            int row = g >> 4;         // 0..63
            int d   = (g & 15) * 4;
            float4 kv = *(const float4*)(kbase + (size_t)row * Dn + d);
            Ks[(d + 0) * KPAD + row] = kv.x;
            Ks[(d + 1) * KPAD + row] = kv.y;
            Ks[(d + 2) * KPAD + row] = kv.z;
            Ks[(d + 3) * KPAD + row] = kv.w;
            float4 vv = *(const float4*)(vbase + (size_t)row * Dn + d);
            *(float4*)&Vs[row * KPAD + d] = vv;
        }
        __syncthreads();

        // Phase 1: S[128,64] = Q @ K^T  (contract over d)
        float s[8][4];
#pragma unroll
        for (int i = 0; i < 8; i++)
#pragma unroll
            for (int j = 0; j < 4; j++) s[i][j] = 0.f;

#pragma unroll 8
        for (int d = 0; d < 64; d++) {
            float a[8], bb[4];
            *(float4*)&a[0]  = *(const float4*)&Qs[d * QPAD + ty * 8];
            *(float4*)&a[4]  = *(const float4*)&Qs[d * QPAD + ty * 8 + 4];
            *(float4*)&bb[0] = *(const float4*)&Ks[d * KPAD + tx * 4];
#pragma unroll
            for (int i = 0; i < 8; i++)
#pragma unroll
                for (int j = 0; j < 4; j++)
                    s[i][j] += a[i] * bb[j];
        }

        // Scale + rel-pos bias + online softmax update
#pragma unroll
        for (int i = 0; i < 8; i++) {
            int qi = q0 + ty * 8 + i;
            float mt = -1e30f;
#pragma unroll
            for (int j = 0; j < 4; j++) {
                int kj  = kt + tx * 4 + j;
                int rel = qi - kj;
                rel = min(max(rel, -MAXREL), MAXREL) + MAXREL;
                s[i][j] = s[i][j] * scale + Bsm[rel];
                mt = fmaxf(mt, s[i][j]);
            }
            // row reduce over the 16-lane tx group (lanes 0-15 / 16-31)
            mt = fmaxf(mt, __shfl_xor_sync(0xffffffffu, mt, 1));
            mt = fmaxf(mt, __shfl_xor_sync(0xffffffffu, mt, 2));
            mt = fmaxf(mt, __shfl_xor_sync(0xffffffffu, mt, 4));
            mt = fmaxf(mt, __shfl_xor_sync(0xffffffffu, mt, 8));
            float m_new = fmaxf(m_i[i], mt);
            float corr  = __expf(m_i[i] - m_new);
            float rs = 0.f;
#pragma unroll
            for (int j = 0; j < 4; j++) {
                float e = __expf(s[i][j] - m_new);
                s[i][j] = e;
                rs += e;
            }
            rs += __shfl_xor_sync(0xffffffffu, rs, 1);
            rs += __shfl_xor_sync(0xffffffffu, rs, 2);
            rs += __shfl_xor_sync(0xffffffffu, rs, 4);
            rs += __shfl_xor_sync(0xffffffffu, rs, 8);
            l_i[i] = l_i[i] * corr + rs;
            m_i[i] = m_new;
#pragma unroll
            for (int j = 0; j < 4; j++) acc_o[i][j] *= corr;
            // store P transposed: Ps[key][row]
#pragma unroll
            for (int j = 0; j < 4; j++)
                Ps[(tx * 4 + j) * QPAD + ty * 8 + i] = s[i][j];
        }
        __syncthreads();

        // Phase 2: O[128,64] += P @ V  (contract over keys)
#pragma unroll 8
        for (int k = 0; k < 64; k++) {
            float pr[8], vv[4];
            *(float4*)&pr[0] = *(const float4*)&Ps[k * QPAD + ty * 8];
            *(float4*)&pr[4] = *(const float4*)&Ps[k * QPAD + ty * 8 + 4];
            *(float4*)&vv[0] = *(const float4*)&Vs[k * KPAD + tx * 4];
#pragma unroll
            for (int i = 0; i < 8; i++)
#pragma unroll
                for (int j = 0; j < 4; j++)
                    acc_o[i][j] += pr[i] * vv[j];
        }
    }

    // Epilogue: normalize and write ctx[b, q, h*64 + d]
    float* obase = Ctx + ((size_t)(b * Tn + q0)) * Dn + h * HDn;
#pragma unroll
    for (int i = 0; i < 8; i++) {
        float inv = 1.0f / l_i[i];
        float4 o;
        o.x = acc_o[i][0] * inv;
        o.y = acc_o[i][1] * inv;
        o.z = acc_o[i][2] * inv;
        o.w = acc_o[i][3] * inv;
        *(float4*)(obase + (size_t)(ty * 8 + i) * Dn + tx * 4) = o;
    }
}

// ---------------------------------------------------------------------------
// Host launcher (graph-capturable: kernel launches only)
// ---------------------------------------------------------------------------
extern "C" void kernel_launch(void* const* d_in, const int* in_sizes, int n_in,
                              void* d_out, int out_size)
{
    const float* x   = (const float*)d_in[0];
    const float* w_q = (const float*)d_in[1];
    const float* b_q = (const float*)d_in[2];
    const float* w_k = (const float*)d_in[3];
    const float* b_k = (const float*)d_in[4];
    const float* w_v = (const float*)d_in[5];
    const float* b_v = (const float*)d_in[6];
    const float* w_o = (const float*)d_in[7];
    const float* b_o = (const float*)d_in[8];
    const float* bt  = (const float*)d_in[9];
    float* out = (float*)d_out;

    float *qp, *kp, *vp, *cp;
    cudaGetSymbolAddress((void**)&qp, g_q);
    cudaGetSymbolAddress((void**)&kp, g_k);
    cudaGetSymbolAddress((void**)&vp, g_v);
    cudaGetSymbolAddress((void**)&cp, g_ctx);

    const int attn_smem = ATTN_SMEM_FLOATS * (int)sizeof(float);
    cudaFuncSetAttribute(attn_kernel,
                         cudaFuncAttributeMaxDynamicSharedMemorySize, attn_smem);

    // 1) head-averaged bias table
    bias_avg_kernel<<<1, 288>>>(bt);

    // 2) Q/K/V projections
    dim3 ggrid(Mrows / GBM, Dn / GBN);   // (64, 6)
    sgemm_nt<<<ggrid, 256>>>(x, w_q, b_q, qp, Mrows, Dn, Dn);
    sgemm_nt<<<ggrid, 256>>>(x, w_k, b_k, kp, Mrows, Dn, Dn);
    sgemm_nt<<<ggrid, 256>>>(x, w_v, b_v, vp, Mrows, Dn, Dn);

    // 3) attention
    dim3 agrid(Tn / ABQ, Hn, Bn);        // (16, 12, 4)
    attn_kernel<<<agrid, 256, attn_smem>>>(qp, kp, vp, cp);

    // 4) output projection
    sgemm_nt<<<ggrid, 256>>>(cp, w_o, b_o, out, Mrows, Dn, Dn);
}

// round 5
// speedup vs baseline: 1.3091x; 1.3091x over previous
#include <cuda_runtime.h>
#include <cuda_bf16.h>
#include <cstdint>

// Problem constants
#define Bn      4
#define Tn      2048
#define Dn      768
#define Hn      12
#define HDn     64
#define MAXREL  128
#define Mrows   (Bn * Tn)   // 8192

// ---------------------------------------------------------------------------
// Scratch (alloc-free: __device__ globals)
// ---------------------------------------------------------------------------
__device__ __align__(16) float g_q[Mrows * Dn];
__device__ __align__(16) float g_k[Mrows * Dn];
__device__ __align__(16) float g_v[Mrows * Dn];
__device__ __align__(16) float g_ctx[Mrows * Dn];
__device__ float g_bias[2 * MAXREL + 1];

// bf16 hi/lo split scratch
__device__ __align__(16) __nv_bfloat16 g_xh[Mrows * Dn];
__device__ __align__(16) __nv_bfloat16 g_xl[Mrows * Dn];
__device__ __align__(16) __nv_bfloat16 g_ch[Mrows * Dn];
__device__ __align__(16) __nv_bfloat16 g_cl[Mrows * Dn];
__device__ __align__(16) __nv_bfloat16 g_wh[4][Dn * Dn];
__device__ __align__(16) __nv_bfloat16 g_wl[4][Dn * Dn];

// ---------------------------------------------------------------------------
// Helpers
// ---------------------------------------------------------------------------
__device__ __forceinline__ uint32_t smem_u32(const void* p) {
    uint32_t a;
    asm("{ .reg .u64 t; cvta.to.shared.u64 t, %1; cvt.u32.u64 %0, t; }"
        : "=r"(a) : "l"(p));
    return a;
}

__device__ __forceinline__ void ldmx4(uint32_t* r, uint32_t addr) {
    asm volatile("ldmatrix.sync.aligned.m8n8.x4.shared.b16 {%0,%1,%2,%3}, [%4];"
        : "=r"(r[0]), "=r"(r[1]), "=r"(r[2]), "=r"(r[3]) : "r"(addr));
}
__device__ __forceinline__ void mma_bf16(float* d, const uint32_t* a,
                                         uint32_t b0, uint32_t b1) {
    asm volatile("mma.sync.aligned.m16n8k16.row.col.f32.bf16.bf16.f32 "
        "{%0,%1,%2,%3}, {%4,%5,%6,%7}, {%8,%9}, {%0,%1,%2,%3};"
        : "+f"(d[0]), "+f"(d[1]), "+f"(d[2]), "+f"(d[3])
        : "r"(a[0]), "r"(a[1]), "r"(a[2]), "r"(a[3]), "r"(b0), "r"(b1));
}

// ---------------------------------------------------------------------------
// Kernel: head-average of bias_table -> g_bias[257]
// ---------------------------------------------------------------------------
__global__ void bias_avg_kernel(const float* __restrict__ bt) {
    int i = threadIdx.x;
    if (i < 2 * MAXREL + 1) {
        float s = 0.f;
#pragma unroll
        for (int h = 0; h < Hn; h++) s += bt[i * Hn + h];
        g_bias[i] = s * (1.0f / Hn);
    }
}

// ---------------------------------------------------------------------------
// Kernel: fp32 -> bf16 hi/lo split (x ~= hi + lo to ~2^-17)
// ---------------------------------------------------------------------------
__global__ void split_bf16_kernel(const float* __restrict__ in,
                                  __nv_bfloat16* __restrict__ hi,
                                  __nv_bfloat16* __restrict__ lo, int n4) {
    int i = blockIdx.x * blockDim.x + threadIdx.x;
    if (i < n4) {
        float4 v = ((const float4*)in)[i];
        float f0 = v.x, f1 = v.y, f2 = v.z, f3 = v.w;
        __nv_bfloat16 h0 = __float2bfloat16_rn(f0);
        __nv_bfloat16 h1 = __float2bfloat16_rn(f1);
        __nv_bfloat16 h2 = __float2bfloat16_rn(f2);
        __nv_bfloat16 h3 = __float2bfloat16_rn(f3);
        __nv_bfloat16 l0 = __float2bfloat16_rn(f0 - __bfloat162float(h0));
        __nv_bfloat16 l1 = __float2bfloat16_rn(f1 - __bfloat162float(h1));
        __nv_bfloat16 l2 = __float2bfloat16_rn(f2 - __bfloat162float(h2));
        __nv_bfloat16 l3 = __float2bfloat16_rn(f3 - __bfloat162float(h3));
        __nv_bfloat162* H = (__nv_bfloat162*)(hi + 4 * (size_t)i);
        __nv_bfloat162* L = (__nv_bfloat162*)(lo + 4 * (size_t)i);
        H[0] = __halves2bfloat162(h0, h1);
        H[1] = __halves2bfloat162(h2, h3);
        L[0] = __halves2bfloat162(l0, l1);
        L[1] = __halves2bfloat162(l2, l3);
    }
}

// ---------------------------------------------------------------------------
// Kernel: mma.sync bf16x3 GEMM  C[M,N] = A @ W^T + bias
// M=8192, N=768, K=768. Block tile 128x128x32, 8 warps (4M x 2N),
// warp tile 32x64. Synchronous smem staging + register prefetch.
// Staging: 2 threads per row, 32B each -> full 64B (32 bf16) row coverage.
// ---------------------------------------------------------------------------
#define BM 128
#define BN 128
#define BKC 32
#define NCHUNK (Dn / BKC)            // 24
#define LDE 40                        // smem row stride (elements) = 80 bytes
#define GT_TILE_B (128 * LDE * 2)     // 10240 bytes per tile
// tiles: Ah @0, Al @10240, Bh @20480, Bl @30720; total 40960 B (static smem)

__global__ __launch_bounds__(256) void gemm_mma(
    const __nv_bfloat16* __restrict__ Ah, const __nv_bfloat16* __restrict__ Al,
    const __nv_bfloat16* __restrict__ Bh, const __nv_bfloat16* __restrict__ Bl,
    const float* __restrict__ bias, float* __restrict__ C)
{
    __shared__ __align__(16) char sm[4 * GT_TILE_B];
    const int t    = threadIdx.x;
    const int lane = t & 31;
    const int w    = t >> 5;
    const int wm   = w & 3;           // 0..3 (M, 32 rows each)
    const int wn   = w >> 2;          // 0..1 (N, 64 cols each)
    const int n0   = blockIdx.x * BN;
    const int m0   = blockIdx.y * BM;
    const uint32_t sbase = smem_u32(sm);

    float acc[2][8][4];
#pragma unroll
    for (int i = 0; i < 2; i++)
#pragma unroll
        for (int j = 0; j < 8; j++)
#pragma unroll
            for (int q = 0; q < 4; q++) acc[i][j][q] = 0.f;

    // staging: srow = t>>1 (0..127), shalf = t&1 -> 32B half of the 64B row
    const int srow  = t >> 1;
    const int shalf = t & 1;
    const __nv_bfloat16* gsrc[4];
    gsrc[0] = Ah + (size_t)(m0 + srow) * Dn + shalf * 16;
    gsrc[1] = Al + (size_t)(m0 + srow) * Dn + shalf * 16;
    gsrc[2] = Bh + (size_t)(n0 + srow) * Dn + shalf * 16;
    gsrc[3] = Bl + (size_t)(n0 + srow) * Dn + shalf * 16;
    const int soff = srow * (LDE * 2) + shalf * 32;   // byte offset in tile

    uint4 v[4][2];
#pragma unroll
    for (int u = 0; u < 4; u++) {
        v[u][0] = *(const uint4*)(gsrc[u]);
        v[u][1] = *(const uint4*)(gsrc[u] + 8);
    }

    for (int c = 0; c < NCHUNK; c++) {
        // store prefetched chunk to smem (full 64B per row across 2 threads)
#pragma unroll
        for (int u = 0; u < 4; u++) {
            *(uint4*)(sm + u * GT_TILE_B + soff)      = v[u][0];
            *(uint4*)(sm + u * GT_TILE_B + soff + 16) = v[u][1];
        }
        __syncthreads();

        // prefetch next chunk
        if (c + 1 < NCHUNK) {
            const int koff = (c + 1) * BKC;
#pragma unroll
            for (int u = 0; u < 4; u++) {
                v[u][0] = *(const uint4*)(gsrc[u] + koff);
                v[u][1] = *(const uint4*)(gsrc[u] + koff + 8);
            }
        }

        const uint32_t sA  = sbase;
        const uint32_t sAl = sbase + GT_TILE_B;
        const uint32_t sB  = sbase + 2 * GT_TILE_B;
        const uint32_t sBl = sbase + 3 * GT_TILE_B;
#pragma unroll
        for (int kk = 0; kk < 2; kk++) {
            // A fragments: x4 = (m0-7,k0-7),(m8-15,k0-7),(m0-7,k8-15),(m8-15,k8-15)
            uint32_t ah[2][4], al[2][4];
            const uint32_t arow = wm * 32 + (lane & 15);
            const uint32_t acol = (kk * 16 + (lane >> 4) * 8) * 2;   // bytes
#pragma unroll
            for (int mi = 0; mi < 2; mi++) {
                ldmx4(ah[mi], sA  + (arow + mi * 16) * (LDE * 2) + acol);
                ldmx4(al[mi], sAl + (arow + mi * 16) * (LDE * 2) + acol);
            }
            // B fragments (non-trans; W rows are n): x4 covers 2 n-tiles x 2 k-halves
            const uint32_t g     = lane >> 3;                         // 0..3
            const uint32_t brow0 = wn * 64 + (g >> 1) * 8 + (lane & 7);
            const uint32_t bcol  = (kk * 16 + (g & 1) * 8) * 2;       // bytes
#pragma unroll
            for (int np = 0; np < 4; np++) {
                uint32_t bh[4], bl[4];
                ldmx4(bh, sB  + (brow0 + np * 16) * (LDE * 2) + bcol);
                ldmx4(bl, sBl + (brow0 + np * 16) * (LDE * 2) + bcol);
#pragma unroll
                for (int sub = 0; sub < 2; sub++) {
                    const int nt = np * 2 + sub;
                    uint32_t bh0 = bh[sub * 2], bh1 = bh[sub * 2 + 1];
                    uint32_t bl0 = bl[sub * 2], bl1 = bl[sub * 2 + 1];
#pragma unroll
                    for (int mi = 0; mi < 2; mi++) {
                        mma_bf16(acc[mi][nt], ah[mi], bh0, bh1);
                        mma_bf16(acc[mi][nt], al[mi], bh0, bh1);
                        mma_bf16(acc[mi][nt], ah[mi], bl0, bl1);
                    }
                }
            }
        }
        __syncthreads();
    }

    // epilogue: direct stores from fragments + bias
    const int colq = 2 * (lane & 3);
#pragma unroll
    for (int nt = 0; nt < 8; nt++) {
        const int colg = n0 + wn * 64 + nt * 8 + colq;
        const float2 bv = *(const float2*)(bias + colg);
#pragma unroll
        for (int mi = 0; mi < 2; mi++) {
            const int r0 = m0 + wm * 32 + mi * 16 + (lane >> 2);
            float2 o0, o1;
            o0.x = acc[mi][nt][0] + bv.x;
            o0.y = acc[mi][nt][1] + bv.y;
            o1.x = acc[mi][nt][2] + bv.x;
            o1.y = acc[mi][nt][3] + bv.y;
            *(float2*)(C + (size_t)r0 * Dn + colg) = o0;
            *(float2*)(C + (size_t)(r0 + 8) * Dn + colg) = o1;
        }
    }
}

// ---------------------------------------------------------------------------
// Kernel: flash attention (fp32) — unchanged (known good)
// ---------------------------------------------------------------------------
#define ABQ  128
#define ABK  64
#define QPAD (ABQ + 4)
#define KPAD (ABK + 4)
#define ATTN_SMEM_FLOATS (64 * QPAD + 64 * KPAD + 64 * KPAD + 64 * QPAD + 260)

__global__ __launch_bounds__(256) void attn_kernel(
    const float* __restrict__ Q, const float* __restrict__ Kp,
    const float* __restrict__ Vp, float* __restrict__ Ctx)
{
    extern __shared__ __align__(16) float smf[];
    float* Qs  = smf;
    float* Ks  = Qs + 64 * QPAD;
    float* Vs  = Ks + 64 * KPAD;
    float* Ps  = Vs + 64 * KPAD;
    float* Bsm = Ps + 64 * QPAD;

    const int t  = threadIdx.x;
    const int tx = t & 15;
    const int ty = t >> 4;
    const int q0 = blockIdx.x * ABQ;
    const int h  = blockIdx.y;
    const int b  = blockIdx.z;

    for (int i = t; i < 2 * MAXREL + 1; i += 256) Bsm[i] = g_bias[i];

    const float* qbase = Q + ((size_t)(b * Tn + q0)) * Dn + h * HDn;
#pragma unroll
    for (int u = 0; u < 8; u++) {
        int g   = t * 8 + u;
        int row = g >> 4;
        int d   = (g & 15) * 4;
        float4 v = *(const float4*)(qbase + (size_t)row * Dn + d);
        Qs[(d + 0) * QPAD + row] = v.x;
        Qs[(d + 1) * QPAD + row] = v.y;
        Qs[(d + 2) * QPAD + row] = v.z;
        Qs[(d + 3) * QPAD + row] = v.w;
    }

    float m_i[8], l_i[8], acc_o[8][4];
#pragma unroll
    for (int i = 0; i < 8; i++) {
        m_i[i] = -1e30f; l_i[i] = 0.f;
#pragma unroll
        for (int j = 0; j < 4; j++) acc_o[i][j] = 0.f;
    }

    const float scale = 0.125f;

    for (int kt = 0; kt < Tn; kt += ABK) {
        __syncthreads();

        const float* kbase = Kp + ((size_t)(b * Tn + kt)) * Dn + h * HDn;
        const float* vbase = Vp + ((size_t)(b * Tn + kt)) * Dn + h * HDn;
#pragma unroll
        for (int u = 0; u < 4; u++) {
            int g   = t * 4 + u;
            int row = g >> 4;
            int d   = (g & 15) * 4;
            float4 kv = *(const float4*)(kbase + (size_t)row * Dn + d);
            Ks[(d + 0) * KPAD + row] = kv.x;
            Ks[(d + 1) * KPAD + row] = kv.y;
            Ks[(d + 2) * KPAD + row] = kv.z;
            Ks[(d + 3) * KPAD + row] = kv.w;
            float4 vv = *(const float4*)(vbase + (size_t)row * Dn + d);
            *(float4*)&Vs[row * KPAD + d] = vv;
        }
        __syncthreads();

        float s[8][4];
#pragma unroll
        for (int i = 0; i < 8; i++)
#pragma unroll
            for (int j = 0; j < 4; j++) s[i][j] = 0.f;

#pragma unroll 8
        for (int d = 0; d < 64; d++) {
            float a[8], bb[4];
            *(float4*)&a[0]  = *(const float4*)&Qs[d * QPAD + ty * 8];
            *(float4*)&a[4]  = *(const float4*)&Qs[d * QPAD + ty * 8 + 4];
            *(float4*)&bb[0] = *(const float4*)&Ks[d * KPAD + tx * 4];
#pragma unroll
            for (int i = 0; i < 8; i++)
#pragma unroll
                for (int j = 0; j < 4; j++)
                    s[i][j] += a[i] * bb[j];
        }

#pragma unroll
        for (int i = 0; i < 8; i++) {
            int qi = q0 + ty * 8 + i;
            float mt = -1e30f;
#pragma unroll
            for (int j = 0; j < 4; j++) {
                int kj  = kt + tx * 4 + j;
                int rel = qi - kj;
                rel = min(max(rel, -MAXREL), MAXREL) + MAXREL;
                s[i][j] = s[i][j] * scale + Bsm[rel];
                mt = fmaxf(mt, s[i][j]);
            }
            mt = fmaxf(mt, __shfl_xor_sync(0xffffffffu, mt, 1));
            mt = fmaxf(mt, __shfl_xor_sync(0xffffffffu, mt, 2));
            mt = fmaxf(mt, __shfl_xor_sync(0xffffffffu, mt, 4));
            mt = fmaxf(mt, __shfl_xor_sync(0xffffffffu, mt, 8));
            float m_new = fmaxf(m_i[i], mt);
            float corr  = __expf(m_i[i] - m_new);
            float rs = 0.f;
#pragma unroll
            for (int j = 0; j < 4; j++) {
                float e = __expf(s[i][j] - m_new);
                s[i][j] = e;
                rs += e;
            }
            rs += __shfl_xor_sync(0xffffffffu, rs, 1);
            rs += __shfl_xor_sync(0xffffffffu, rs, 2);
            rs += __shfl_xor_sync(0xffffffffu, rs, 4);
            rs += __shfl_xor_sync(0xffffffffu, rs, 8);
            l_i[i] = l_i[i] * corr + rs;
            m_i[i] = m_new;
#pragma unroll
            for (int j = 0; j < 4; j++) acc_o[i][j] *= corr;
#pragma unroll
            for (int j = 0; j < 4; j++)
                Ps[(tx * 4 + j) * QPAD + ty * 8 + i] = s[i][j];
        }
        __syncthreads();

#pragma unroll 8
        for (int k = 0; k < 64; k++) {
            float pr[8], vv[4];
            *(float4*)&pr[0] = *(const float4*)&Ps[k * QPAD + ty * 8];
            *(float4*)&pr[4] = *(const float4*)&Ps[k * QPAD + ty * 8 + 4];
            *(float4*)&vv[0] = *(const float4*)&Vs[k * KPAD + tx * 4];
#pragma unroll
            for (int i = 0; i < 8; i++)
#pragma unroll
                for (int j = 0; j < 4; j++)
                    acc_o[i][j] += pr[i] * vv[j];
        }
    }

    float* obase = Ctx + ((size_t)(b * Tn + q0)) * Dn + h * HDn;
#pragma unroll
    for (int i = 0; i < 8; i++) {
        float inv = 1.0f / l_i[i];
        float4 o;
        o.x = acc_o[i][0] * inv;
        o.y = acc_o[i][1] * inv;
        o.z = acc_o[i][2] * inv;
        o.w = acc_o[i][3] * inv;
        *(float4*)(obase + (size_t)(ty * 8 + i) * Dn + tx * 4) = o;
    }
}

// ---------------------------------------------------------------------------
// Host launcher
// ---------------------------------------------------------------------------
extern "C" void kernel_launch(void* const* d_in, const int* in_sizes, int n_in,
                              void* d_out, int out_size)
{
    const float* x   = (const float*)d_in[0];
    const float* w_q = (const float*)d_in[1];
    const float* b_q = (const float*)d_in[2];
    const float* w_k = (const float*)d_in[3];
    const float* b_k = (const float*)d_in[4];
    const float* w_v = (const float*)d_in[5];
    const float* b_v = (const float*)d_in[6];
    const float* w_o = (const float*)d_in[7];
    const float* b_o = (const float*)d_in[8];
    const float* bt  = (const float*)d_in[9];
    float* out = (float*)d_out;

    float *qp, *kp, *vp, *cp;
    cudaGetSymbolAddress((void**)&qp, g_q);
    cudaGetSymbolAddress((void**)&kp, g_k);
    cudaGetSymbolAddress((void**)&vp, g_v);
    cudaGetSymbolAddress((void**)&cp, g_ctx);
    __nv_bfloat16 *xh, *xl, *ch, *cl, *wh, *wl;
    cudaGetSymbolAddress((void**)&xh, g_xh);
    cudaGetSymbolAddress((void**)&xl, g_xl);
    cudaGetSymbolAddress((void**)&ch, g_ch);
    cudaGetSymbolAddress((void**)&cl, g_cl);
    cudaGetSymbolAddress((void**)&wh, g_wh);
    cudaGetSymbolAddress((void**)&wl, g_wl);

    const int attn_smem = ATTN_SMEM_FLOATS * (int)sizeof(float);
    cudaFuncSetAttribute(attn_kernel,
                         cudaFuncAttributeMaxDynamicSharedMemorySize, attn_smem);

    // 1) head-averaged bias table
    bias_avg_kernel<<<1, 288>>>(bt);

    // 2) split inputs to bf16 hi/lo
    const int n4x = Mrows * Dn / 4;
    const int n4w = Dn * Dn / 4;
    split_bf16_kernel<<<(n4x + 255) / 256, 256>>>(x, xh, xl, n4x);
    split_bf16_kernel<<<(n4w + 255) / 256, 256>>>(w_q, wh + 0 * (size_t)Dn * Dn, wl + 0 * (size_t)Dn * Dn, n4w);
    split_bf16_kernel<<<(n4w + 255) / 256, 256>>>(w_k, wh + 1 * (size_t)Dn * Dn, wl + 1 * (size_t)Dn * Dn, n4w);
    split_bf16_kernel<<<(n4w + 255) / 256, 256>>>(w_v, wh + 2 * (size_t)Dn * Dn, wl + 2 * (size_t)Dn * Dn, n4w);
    split_bf16_kernel<<<(n4w + 255) / 256, 256>>>(w_o, wh + 3 * (size_t)Dn * Dn, wl + 3 * (size_t)Dn * Dn, n4w);

    // 3) Q/K/V projections (mma.sync bf16x3)
    dim3 ggrid(Dn / BN, Mrows / BM);      // (6, 64)
    gemm_mma<<<ggrid, 256>>>(xh, xl, wh + 0 * (size_t)Dn * Dn, wl + 0 * (size_t)Dn * Dn, b_q, qp);
    gemm_mma<<<ggrid, 256>>>(xh, xl, wh + 1 * (size_t)Dn * Dn, wl + 1 * (size_t)Dn * Dn, b_k, kp);
    gemm_mma<<<ggrid, 256>>>(xh, xl, wh + 2 * (size_t)Dn * Dn, wl + 2 * (size_t)Dn * Dn, b_v, vp);

    // 4) attention (fp32)
    dim3 agrid(Tn / ABQ, Hn, Bn);         // (16, 12, 4)
    attn_kernel<<<agrid, 256, attn_smem>>>(qp, kp, vp, cp);

    // 5) split ctx, output projection
    split_bf16_kernel<<<(n4x + 255) / 256, 256>>>(cp, ch, cl, n4x);
    gemm_mma<<<ggrid, 256>>>(ch, cl, wh + 3 * (size_t)Dn * Dn, wl + 3 * (size_t)Dn * Dn, b_o, out);
}

// round 6
// speedup vs baseline: 2.1965x; 1.6779x over previous
#include <cuda_runtime.h>
#include <cuda_bf16.h>
#include <cstdint>

// Problem constants
#define Bn      4
#define Tn      2048
#define Dn      768
#define Hn      12
#define HDn     64
#define MAXREL  128
#define Mrows   (Bn * Tn)   // 8192

// ---------------------------------------------------------------------------
// Scratch (alloc-free: __device__ globals)
// ---------------------------------------------------------------------------
__device__ float g_bias[2 * MAXREL + 1];

__device__ __align__(16) __nv_bfloat16 g_xh[Mrows * Dn];
__device__ __align__(16) __nv_bfloat16 g_xl[Mrows * Dn];
__device__ __align__(16) __nv_bfloat16 g_qh[Mrows * Dn];
__device__ __align__(16) __nv_bfloat16 g_ql[Mrows * Dn];
__device__ __align__(16) __nv_bfloat16 g_kh[Mrows * Dn];
__device__ __align__(16) __nv_bfloat16 g_kl[Mrows * Dn];
__device__ __align__(16) __nv_bfloat16 g_vh[Mrows * Dn];
__device__ __align__(16) __nv_bfloat16 g_vl[Mrows * Dn];
__device__ __align__(16) __nv_bfloat16 g_ch[Mrows * Dn];
__device__ __align__(16) __nv_bfloat16 g_cl[Mrows * Dn];
__device__ __align__(16) __nv_bfloat16 g_wh[4][Dn * Dn];
__device__ __align__(16) __nv_bfloat16 g_wl[4][Dn * Dn];

// ---------------------------------------------------------------------------
// Helpers
// ---------------------------------------------------------------------------
__device__ __forceinline__ uint32_t smem_u32(const void* p) {
    uint32_t a;
    asm("{ .reg .u64 t; cvta.to.shared.u64 t, %1; cvt.u32.u64 %0, t; }"
        : "=r"(a) : "l"(p));
    return a;
}
__device__ __forceinline__ void ldmx4(uint32_t* r, uint32_t addr) {
    asm volatile("ldmatrix.sync.aligned.m8n8.x4.shared.b16 {%0,%1,%2,%3}, [%4];"
        : "=r"(r[0]), "=r"(r[1]), "=r"(r[2]), "=r"(r[3]) : "r"(addr));
}
__device__ __forceinline__ void ldmx4t(uint32_t* r, uint32_t addr) {
    asm volatile("ldmatrix.sync.aligned.m8n8.x4.trans.shared.b16 {%0,%1,%2,%3}, [%4];"
        : "=r"(r[0]), "=r"(r[1]), "=r"(r[2]), "=r"(r[3]) : "r"(addr));
}
__device__ __forceinline__ void mma_bf16(float* d, const uint32_t* a,
                                         uint32_t b0, uint32_t b1) {
    asm volatile("mma.sync.aligned.m16n8k16.row.col.f32.bf16.bf16.f32 "
        "{%0,%1,%2,%3}, {%4,%5,%6,%7}, {%8,%9}, {%0,%1,%2,%3};"
        : "+f"(d[0]), "+f"(d[1]), "+f"(d[2]), "+f"(d[3])
        : "r"(a[0]), "r"(a[1]), "r"(a[2]), "r"(a[3]), "r"(b0), "r"(b1));
}
__device__ __forceinline__ uint32_t pack_hi(float a, float b) {
    __nv_bfloat162 h = __halves2bfloat162(__float2bfloat16_rn(a), __float2bfloat16_rn(b));
    return *(uint32_t*)&h;
}

// ---------------------------------------------------------------------------
// Kernel: head-average of bias_table -> g_bias[257]
// ---------------------------------------------------------------------------
__global__ void bias_avg_kernel(const float* __restrict__ bt) {
    int i = threadIdx.x;
    if (i < 2 * MAXREL + 1) {
        float s = 0.f;
#pragma unroll
        for (int h = 0; h < Hn; h++) s += bt[i * Hn + h];
        g_bias[i] = s * (1.0f / Hn);
    }
}

// ---------------------------------------------------------------------------
// Kernel: fp32 -> bf16 hi/lo split
// ---------------------------------------------------------------------------
__global__ void split_bf16_kernel(const float* __restrict__ in,
                                  __nv_bfloat16* __restrict__ hi,
                                  __nv_bfloat16* __restrict__ lo, int n4) {
    int i = blockIdx.x * blockDim.x + threadIdx.x;
    if (i < n4) {
        float4 v = ((const float4*)in)[i];
        __nv_bfloat16 h0 = __float2bfloat16_rn(v.x);
        __nv_bfloat16 h1 = __float2bfloat16_rn(v.y);
        __nv_bfloat16 h2 = __float2bfloat16_rn(v.z);
        __nv_bfloat16 h3 = __float2bfloat16_rn(v.w);
        __nv_bfloat16 l0 = __float2bfloat16_rn(v.x - __bfloat162float(h0));
        __nv_bfloat16 l1 = __float2bfloat16_rn(v.y - __bfloat162float(h1));
        __nv_bfloat16 l2 = __float2bfloat16_rn(v.z - __bfloat162float(h2));
        __nv_bfloat16 l3 = __float2bfloat16_rn(v.w - __bfloat162float(h3));
        __nv_bfloat162* H = (__nv_bfloat162*)(hi + 4 * (size_t)i);
        __nv_bfloat162* L = (__nv_bfloat162*)(lo + 4 * (size_t)i);
        H[0] = __halves2bfloat162(h0, h1);
        H[1] = __halves2bfloat162(h2, h3);
        L[0] = __halves2bfloat162(l0, l1);
        L[1] = __halves2bfloat162(l2, l3);
    }
}

// ---------------------------------------------------------------------------
// Kernel: mma.sync bf16x3 GEMM  C = A @ W^T + bias
// Epilogue: fp32 out (Cf != 0) OR bf16 hi/lo out (Ch/Cl).
// ---------------------------------------------------------------------------
#define BM 128
#define BN 128
#define BKC 32
#define NCHUNK (Dn / BKC)            // 24
#define LDE 40
#define GT_TILE_B (128 * LDE * 2)     // 10240

__global__ __launch_bounds__(256) void gemm_mma(
    const __nv_bfloat16* __restrict__ Ah, const __nv_bfloat16* __restrict__ Al,
    const __nv_bfloat16* __restrict__ Bh, const __nv_bfloat16* __restrict__ Bl,
    const float* __restrict__ bias, float* __restrict__ Cf,
    __nv_bfloat16* __restrict__ Ch, __nv_bfloat16* __restrict__ Cl)
{
    __shared__ __align__(16) char sm[4 * GT_TILE_B];
    const int t    = threadIdx.x;
    const int lane = t & 31;
    const int w    = t >> 5;
    const int wm   = w & 3;
    const int wn   = w >> 2;
    const int n0   = blockIdx.x * BN;
    const int m0   = blockIdx.y * BM;
    const uint32_t sbase = smem_u32(sm);

    float acc[2][8][4];
#pragma unroll
    for (int i = 0; i < 2; i++)
#pragma unroll
        for (int j = 0; j < 8; j++)
#pragma unroll
            for (int q = 0; q < 4; q++) acc[i][j][q] = 0.f;

    const int srow  = t >> 1;
    const int shalf = t & 1;
    const __nv_bfloat16* gsrc[4];
    gsrc[0] = Ah + (size_t)(m0 + srow) * Dn + shalf * 16;
    gsrc[1] = Al + (size_t)(m0 + srow) * Dn + shalf * 16;
    gsrc[2] = Bh + (size_t)(n0 + srow) * Dn + shalf * 16;
    gsrc[3] = Bl + (size_t)(n0 + srow) * Dn + shalf * 16;
    const int soff = srow * (LDE * 2) + shalf * 32;

    uint4 v[4][2];
#pragma unroll
    for (int u = 0; u < 4; u++) {
        v[u][0] = *(const uint4*)(gsrc[u]);
        v[u][1] = *(const uint4*)(gsrc[u] + 8);
    }

    for (int c = 0; c < NCHUNK; c++) {
#pragma unroll
        for (int u = 0; u < 4; u++) {
            *(uint4*)(sm + u * GT_TILE_B + soff)      = v[u][0];
            *(uint4*)(sm + u * GT_TILE_B + soff + 16) = v[u][1];
        }
        __syncthreads();

        if (c + 1 < NCHUNK) {
            const int koff = (c + 1) * BKC;
#pragma unroll
            for (int u = 0; u < 4; u++) {
                v[u][0] = *(const uint4*)(gsrc[u] + koff);
                v[u][1] = *(const uint4*)(gsrc[u] + koff + 8);
            }
        }

        const uint32_t sA  = sbase;
        const uint32_t sAl = sbase + GT_TILE_B;
        const uint32_t sB  = sbase + 2 * GT_TILE_B;
        const uint32_t sBl = sbase + 3 * GT_TILE_B;
#pragma unroll
        for (int kk = 0; kk < 2; kk++) {
            uint32_t ah[2][4], al[2][4];
            const uint32_t arow = wm * 32 + (lane & 15);
            const uint32_t acol = (kk * 16 + (lane >> 4) * 8) * 2;
#pragma unroll
            for (int mi = 0; mi < 2; mi++) {
                ldmx4(ah[mi], sA  + (arow + mi * 16) * (LDE * 2) + acol);
                ldmx4(al[mi], sAl + (arow + mi * 16) * (LDE * 2) + acol);
            }
            const uint32_t g     = lane >> 3;
            const uint32_t brow0 = wn * 64 + (g >> 1) * 8 + (lane & 7);
            const uint32_t bcol  = (kk * 16 + (g & 1) * 8) * 2;
#pragma unroll
            for (int np = 0; np < 4; np++) {
                uint32_t bh[4], bl[4];
                ldmx4(bh, sB  + (brow0 + np * 16) * (LDE * 2) + bcol);
                ldmx4(bl, sBl + (brow0 + np * 16) * (LDE * 2) + bcol);
#pragma unroll
                for (int sub = 0; sub < 2; sub++) {
                    const int nt = np * 2 + sub;
                    uint32_t bh0 = bh[sub * 2], bh1 = bh[sub * 2 + 1];
                    uint32_t bl0 = bl[sub * 2], bl1 = bl[sub * 2 + 1];
#pragma unroll
                    for (int mi = 0; mi < 2; mi++) {
                        mma_bf16(acc[mi][nt], ah[mi], bh0, bh1);
                        mma_bf16(acc[mi][nt], al[mi], bh0, bh1);
                        mma_bf16(acc[mi][nt], ah[mi], bl0, bl1);
                    }
                }
            }
        }
        __syncthreads();
    }

    const int colq = 2 * (lane & 3);
#pragma unroll
    for (int nt = 0; nt < 8; nt++) {
        const int colg = n0 + wn * 64 + nt * 8 + colq;
        const float2 bv = *(const float2*)(bias + colg);
#pragma unroll
        for (int mi = 0; mi < 2; mi++) {
            const int r0 = m0 + wm * 32 + mi * 16 + (lane >> 2);
            float x0 = acc[mi][nt][0] + bv.x;
            float x1 = acc[mi][nt][1] + bv.y;
            float x2 = acc[mi][nt][2] + bv.x;
            float x3 = acc[mi][nt][3] + bv.y;
            if (Cf) {
                *(float2*)(Cf + (size_t)r0 * Dn + colg) = make_float2(x0, x1);
                *(float2*)(Cf + (size_t)(r0 + 8) * Dn + colg) = make_float2(x2, x3);
            } else {
                // bf16 hi/lo epilogue
                float h0 = __bfloat162float(__float2bfloat16_rn(x0));
                float h1 = __bfloat162float(__float2bfloat16_rn(x1));
                float h2 = __bfloat162float(__float2bfloat16_rn(x2));
                float h3 = __bfloat162float(__float2bfloat16_rn(x3));
                *(uint32_t*)(Ch + (size_t)r0 * Dn + colg)       = pack_hi(x0, x1);
                *(uint32_t*)(Cl + (size_t)r0 * Dn + colg)       = pack_hi(x0 - h0, x1 - h1);
                *(uint32_t*)(Ch + (size_t)(r0 + 8) * Dn + colg) = pack_hi(x2, x3);
                *(uint32_t*)(Cl + (size_t)(r0 + 8) * Dn + colg) = pack_hi(x2 - h2, x3 - h3);
            }
        }
    }
}

// ---------------------------------------------------------------------------
// Kernel: flash attention, tensor cores, bf16x3 for QK and PV.
// Block: 128 q-rows x (head, batch). 8 warps; warp = 16 q-rows.
// ---------------------------------------------------------------------------
#define ROWB 144                       // smem row pitch bytes (72 bf16)
#define SQH  0
#define SQL  (SQH + 128 * ROWB)        // 18432
#define SKH  (SQL + 128 * ROWB)        // 36864
#define SKL  (SKH + 64 * ROWB)         // 46080
#define SVH  (SKL + 64 * ROWB)         // 55296
#define SVL  (SVH + 64 * ROWB)         // 64512
#define SPH  (SVL + 64 * ROWB)         // 73728
#define SPL  (SPH + 128 * ROWB)        // 92160
#define SBIAS (SPL + 128 * ROWB)       // 110592
#define ATT_SMEM (SBIAS + 257 * 4 + 12)  // 111632

__global__ __launch_bounds__(256, 1) void attn_mma(
    const __nv_bfloat16* __restrict__ Qh, const __nv_bfloat16* __restrict__ Ql,
    const __nv_bfloat16* __restrict__ Kh, const __nv_bfloat16* __restrict__ Kl,
    const __nv_bfloat16* __restrict__ Vh, const __nv_bfloat16* __restrict__ Vl,
    __nv_bfloat16* __restrict__ Ch, __nv_bfloat16* __restrict__ Cl)
{
    extern __shared__ __align__(16) char sm[];
    const uint32_t sb = smem_u32(sm);
    float* Bsm = (float*)(sm + SBIAS);

    const int t    = threadIdx.x;
    const int lane = t & 31;
    const int wm   = t >> 5;           // warp id = q-row group (16 rows)
    const int q0   = blockIdx.x * 128;
    const int h    = blockIdx.y;
    const int b    = blockIdx.z;

    for (int i = t; i < 257; i += 256) Bsm[i] = g_bias[i];

    // stage Q (128 rows x 64 bf16, hi+lo)
#pragma unroll
    for (int u = 0; u < 8; u++) {
        int idx = u * 256 + t;          // 0..2047
        int hl  = idx >> 10;
        int r   = (idx >> 3) & 127;
        int c   = idx & 7;
        const __nv_bfloat16* src = (hl ? Ql : Qh)
            + (size_t)(b * Tn + q0 + r) * Dn + h * HDn + c * 8;
        *(uint4*)(sm + (hl ? SQL : SQH) + r * ROWB + c * 16) = *(const uint4*)src;
    }
    __syncthreads();

    // hoist Q fragments: 4 ksteps x (hi,lo)
    uint32_t qf_h[4][4], qf_l[4][4];
    {
        const uint32_t arow = wm * 16 + (lane & 15);
        const uint32_t acolb = (lane >> 4) * 16;    // bytes of 8-col group
#pragma unroll
        for (int ks = 0; ks < 4; ks++) {
            ldmx4(qf_h[ks], sb + SQH + arow * ROWB + ks * 32 + acolb);
            ldmx4(qf_l[ks], sb + SQL + arow * ROWB + ks * 32 + acolb);
        }
    }

    float m_i[2] = {-1e30f, -1e30f};
    float l_i[2] = {0.f, 0.f};
    float acc[8][4];
#pragma unroll
    for (int dt = 0; dt < 8; dt++)
#pragma unroll
        for (int q = 0; q < 4; q++) acc[dt][q] = 0.f;

    const float scale = 0.125f;
    const int rA = lane >> 2;              // row within warp tile (0..7), +8 for second

    for (int kt = 0; kt < Tn; kt += 64) {
        __syncthreads();   // previous iter's PV reads of K/V done
        // stage K,V (64 rows x 64 bf16, hi+lo)
#pragma unroll
        for (int u = 0; u < 8; u++) {
            int idx = u * 256 + t;       // 0..2047
            int kv  = idx >> 10;
            int hl  = (idx >> 9) & 1;
            int r   = (idx >> 3) & 63;
            int c   = idx & 7;
            const __nv_bfloat16* src =
                (kv ? (hl ? Vl : Vh) : (hl ? Kl : Kh))
                + (size_t)(b * Tn + kt + r) * Dn + h * HDn + c * 8;
            int dof = kv ? (hl ? SVL : SVH) : (hl ? SKL : SKH);
            *(uint4*)(sm + dof + r * ROWB + c * 16) = *(const uint4*)src;
        }
        __syncthreads();

        // ---- S = Q K^T (3-pass split) ----
        float s[8][4];
#pragma unroll
        for (int nt = 0; nt < 8; nt++)
#pragma unroll
            for (int q = 0; q < 4; q++) s[nt][q] = 0.f;

        const uint32_t g     = lane >> 3;
        const uint32_t brow  = (g >> 1) * 8 + (lane & 7);
        const uint32_t bcolb = (g & 1) * 16;
#pragma unroll
        for (int np = 0; np < 4; np++) {
#pragma unroll
            for (int ks = 0; ks < 4; ks++) {
                uint32_t kh[4], kl[4];
                ldmx4(kh, sb + SKH + (np * 16 + brow) * ROWB + ks * 32 + bcolb);
                ldmx4(kl, sb + SKL + (np * 16 + brow) * ROWB + ks * 32 + bcolb);
#pragma unroll
                for (int sub = 0; sub < 2; sub++) {
                    const int nt = np * 2 + sub;
                    mma_bf16(s[nt], qf_h[ks], kh[sub * 2], kh[sub * 2 + 1]);
                    mma_bf16(s[nt], qf_l[ks], kh[sub * 2], kh[sub * 2 + 1]);
                    mma_bf16(s[nt], qf_h[ks], kl[sub * 2], kl[sub * 2 + 1]);
                }
            }
        }

        // ---- scale + bias + online softmax ----
        float mrow[2] = {-1e30f, -1e30f};
#pragma unroll
        for (int nt = 0; nt < 8; nt++) {
#pragma unroll
            for (int ri = 0; ri < 2; ri++) {
                const int qi = q0 + wm * 16 + rA + ri * 8;
#pragma unroll
                for (int j = 0; j < 2; j++) {
                    const int kj = kt + nt * 8 + 2 * (lane & 3) + j;
                    int rel = qi - kj;
                    rel = min(max(rel, -MAXREL), MAXREL) + MAXREL;
                    float v = s[nt][2 * ri + j] * scale + Bsm[rel];
                    s[nt][2 * ri + j] = v;
                    mrow[ri] = fmaxf(mrow[ri], v);
                }
            }
        }
#pragma unroll
        for (int ri = 0; ri < 2; ri++) {
            mrow[ri] = fmaxf(mrow[ri], __shfl_xor_sync(0xffffffffu, mrow[ri], 1));
            mrow[ri] = fmaxf(mrow[ri], __shfl_xor_sync(0xffffffffu, mrow[ri], 2));
        }
        float m_new[2], corr[2], rsum[2];
#pragma unroll
        for (int ri = 0; ri < 2; ri++) {
            m_new[ri] = fmaxf(m_i[ri], mrow[ri]);
            corr[ri]  = __expf(m_i[ri] - m_new[ri]);
            rsum[ri]  = 0.f;
        }
        // exp, P hi/lo write (warp-local rows)
#pragma unroll
        for (int nt = 0; nt < 8; nt++) {
#pragma unroll
            for (int ri = 0; ri < 2; ri++) {
                float p0 = __expf(s[nt][2 * ri + 0] - m_new[ri]);
                float p1 = __expf(s[nt][2 * ri + 1] - m_new[ri]);
                rsum[ri] += p0 + p1;
                float h0 = __bfloat162float(__float2bfloat16_rn(p0));
                float h1 = __bfloat162float(__float2bfloat16_rn(p1));
                const int prow = wm * 16 + rA + ri * 8;
                const int pcolb = (nt * 8 + 2 * (lane & 3)) * 2;
                *(uint32_t*)(sm + SPH + prow * ROWB + pcolb) = pack_hi(p0, p1);
                *(uint32_t*)(sm + SPL + prow * ROWB + pcolb) = pack_hi(p0 - h0, p1 - h1);
            }
        }
#pragma unroll
        for (int ri = 0; ri < 2; ri++) {
            rsum[ri] += __shfl_xor_sync(0xffffffffu, rsum[ri], 1);
            rsum[ri] += __shfl_xor_sync(0xffffffffu, rsum[ri], 2);
            l_i[ri] = l_i[ri] * corr[ri] + rsum[ri];
            m_i[ri] = m_new[ri];
        }
#pragma unroll
        for (int dt = 0; dt < 8; dt++) {
            acc[dt][0] *= corr[0]; acc[dt][1] *= corr[0];
            acc[dt][2] *= corr[1]; acc[dt][3] *= corr[1];
        }
        __syncwarp();

        // ---- O += P V (3-pass split); V via ldmatrix.trans ----
        const uint32_t arow = wm * 16 + (lane & 15);
        const uint32_t acolb = (lane >> 4) * 16;
        const uint32_t vrow  = (lane & 7) + 8 * ((lane >> 3) & 1);
        const uint32_t vcolb = (lane >> 4) * 16;
#pragma unroll
        for (int ks = 0; ks < 4; ks++) {
            uint32_t pf_h[4], pf_l[4];
            ldmx4(pf_h, sb + SPH + arow * ROWB + ks * 32 + acolb);
            ldmx4(pf_l, sb + SPL + arow * ROWB + ks * 32 + acolb);
#pragma unroll
            for (int np = 0; np < 4; np++) {
                uint32_t vh[4], vl[4];
                ldmx4t(vh, sb + SVH + (ks * 16 + vrow) * ROWB + np * 32 + vcolb);
                ldmx4t(vl, sb + SVL + (ks * 16 + vrow) * ROWB + np * 32 + vcolb);
#pragma unroll
                for (int sub = 0; sub < 2; sub++) {
                    const int dt = np * 2 + sub;
                    mma_bf16(acc[dt], pf_h, vh[sub * 2], vh[sub * 2 + 1]);
                    mma_bf16(acc[dt], pf_l, vh[sub * 2], vh[sub * 2 + 1]);
                    mma_bf16(acc[dt], pf_h, vl[sub * 2], vl[sub * 2 + 1]);
                }
            }
        }
    }

    // epilogue: normalize, write ctx as bf16 hi/lo
    float inv[2] = {1.0f / l_i[0], 1.0f / l_i[1]};
#pragma unroll
    for (int dt = 0; dt < 8; dt++) {
#pragma unroll
        for (int ri = 0; ri < 2; ri++) {
            float o0 = acc[dt][2 * ri + 0] * inv[ri];
            float o1 = acc[dt][2 * ri + 1] * inv[ri];
            float h0 = __bfloat162float(__float2bfloat16_rn(o0));
            float h1 = __bfloat162float(__float2bfloat16_rn(o1));
            const size_t row = (size_t)(b * Tn + q0 + wm * 16 + rA + ri * 8);
            const int col = h * HDn + dt * 8 + 2 * (lane & 3);
            *(uint32_t*)(Ch + row * Dn + col) = pack_hi(o0, o1);
            *(uint32_t*)(Cl + row * Dn + col) = pack_hi(o0 - h0, o1 - h1);
        }
    }
}

// ---------------------------------------------------------------------------
// Host launcher
// ---------------------------------------------------------------------------
extern "C" void kernel_launch(void* const* d_in, const int* in_sizes, int n_in,
                              void* d_out, int out_size)
{
    const float* x   = (const float*)d_in[0];
    const float* w_q = (const float*)d_in[1];
    const float* b_q = (const float*)d_in[2];
    const float* w_k = (const float*)d_in[3];
    const float* b_k = (const float*)d_in[4];
    const float* w_v = (const float*)d_in[5];
    const float* b_v = (const float*)d_in[6];
    const float* w_o = (const float*)d_in[7];
    const float* b_o = (const float*)d_in[8];
    const float* bt  = (const float*)d_in[9];
    float* out = (float*)d_out;

    __nv_bfloat16 *xh, *xl, *qh, *ql, *kh, *kl, *vh, *vl, *ch, *cl, *wh, *wl;
    cudaGetSymbolAddress((void**)&xh, g_xh);
    cudaGetSymbolAddress((void**)&xl, g_xl);
    cudaGetSymbolAddress((void**)&qh, g_qh);
    cudaGetSymbolAddress((void**)&ql, g_ql);
    cudaGetSymbolAddress((void**)&kh, g_kh);
    cudaGetSymbolAddress((void**)&kl, g_kl);
    cudaGetSymbolAddress((void**)&vh, g_vh);
    cudaGetSymbolAddress((void**)&vl, g_vl);
    cudaGetSymbolAddress((void**)&ch, g_ch);
    cudaGetSymbolAddress((void**)&cl, g_cl);
    cudaGetSymbolAddress((void**)&wh, g_wh);
    cudaGetSymbolAddress((void**)&wl, g_wl);

    cudaFuncSetAttribute(attn_mma,
                         cudaFuncAttributeMaxDynamicSharedMemorySize, ATT_SMEM);

    bias_avg_kernel<<<1, 288>>>(bt);

    const int n4x = Mrows * Dn / 4;
    const int n4w = Dn * Dn / 4;
    split_bf16_kernel<<<(n4x + 255) / 256, 256>>>(x, xh, xl, n4x);
    split_bf16_kernel<<<(n4w + 255) / 256, 256>>>(w_q, wh + 0 * (size_t)Dn * Dn, wl + 0 * (size_t)Dn * Dn, n4w);
    split_bf16_kernel<<<(n4w + 255) / 256, 256>>>(w_k, wh + 1 * (size_t)Dn * Dn, wl + 1 * (size_t)Dn * Dn, n4w);
    split_bf16_kernel<<<(n4w + 255) / 256, 256>>>(w_v, wh + 2 * (size_t)Dn * Dn, wl + 2 * (size_t)Dn * Dn, n4w);
    split_bf16_kernel<<<(n4w + 255) / 256, 256>>>(w_o, wh + 3 * (size_t)Dn * Dn, wl + 3 * (size_t)Dn * Dn, n4w);

    dim3 ggrid(Dn / BN, Mrows / BM);      // (6, 64)
    gemm_mma<<<ggrid, 256>>>(xh, xl, wh + 0 * (size_t)Dn * Dn, wl + 0 * (size_t)Dn * Dn, b_q, nullptr, qh, ql);
    gemm_mma<<<ggrid, 256>>>(xh, xl, wh + 1 * (size_t)Dn * Dn, wl + 1 * (size_t)Dn * Dn, b_k, nullptr, kh, kl);
    gemm_mma<<<ggrid, 256>>>(xh, xl, wh + 2 * (size_t)Dn * Dn, wl + 2 * (size_t)Dn * Dn, b_v, nullptr, vh, vl);

    dim3 agrid(Tn / 128, Hn, Bn);         // (16, 12, 4)
    attn_mma<<<agrid, 256, ATT_SMEM>>>(qh, ql, kh, kl, vh, vl, ch, cl);

    gemm_mma<<<ggrid, 256>>>(ch, cl, wh + 3 * (size_t)Dn * Dn, wl + 3 * (size_t)Dn * Dn, b_o, out, nullptr, nullptr);
}

// round 7
// speedup vs baseline: 2.5465x; 1.1594x over previous
#include <cuda_runtime.h>
#include <cuda_bf16.h>
#include <cstdint>

// Problem constants
#define Bn      4
#define Tn      2048
#define Dn      768
#define Hn      12
#define HDn     64
#define MAXREL  128
#define Mrows   (Bn * Tn)   // 8192

// ---------------------------------------------------------------------------
// Scratch (alloc-free: __device__ globals)
// ---------------------------------------------------------------------------
__device__ float g_bias[2 * MAXREL + 1];

__device__ __align__(16) __nv_bfloat16 g_xh[Mrows * Dn];
__device__ __align__(16) __nv_bfloat16 g_xl[Mrows * Dn];
__device__ __align__(16) __nv_bfloat16 g_qh[Mrows * Dn];
__device__ __align__(16) __nv_bfloat16 g_ql[Mrows * Dn];
__device__ __align__(16) __nv_bfloat16 g_kh[Mrows * Dn];
__device__ __align__(16) __nv_bfloat16 g_kl[Mrows * Dn];
__device__ __align__(16) __nv_bfloat16 g_vh[Mrows * Dn];
__device__ __align__(16) __nv_bfloat16 g_vl[Mrows * Dn];
__device__ __align__(16) __nv_bfloat16 g_ch[Mrows * Dn];
__device__ __align__(16) __nv_bfloat16 g_cl[Mrows * Dn];
__device__ __align__(16) __nv_bfloat16 g_wh[4][Dn * Dn];
__device__ __align__(16) __nv_bfloat16 g_wl[4][Dn * Dn];

// ---------------------------------------------------------------------------
// Helpers
// ---------------------------------------------------------------------------
__device__ __forceinline__ uint32_t smem_u32(const void* p) {
    uint32_t a;
    asm("{ .reg .u64 t; cvta.to.shared.u64 t, %1; cvt.u32.u64 %0, t; }"
        : "=r"(a) : "l"(p));
    return a;
}
__device__ __forceinline__ void ldmx4(uint32_t* r, uint32_t addr) {
    asm volatile("ldmatrix.sync.aligned.m8n8.x4.shared.b16 {%0,%1,%2,%3}, [%4];"
        : "=r"(r[0]), "=r"(r[1]), "=r"(r[2]), "=r"(r[3]) : "r"(addr));
}
__device__ __forceinline__ void ldmx4t(uint32_t* r, uint32_t addr) {
    asm volatile("ldmatrix.sync.aligned.m8n8.x4.trans.shared.b16 {%0,%1,%2,%3}, [%4];"
        : "=r"(r[0]), "=r"(r[1]), "=r"(r[2]), "=r"(r[3]) : "r"(addr));
}
__device__ __forceinline__ void mma_bf16(float* d, const uint32_t* a,
                                         uint32_t b0, uint32_t b1) {
    asm volatile("mma.sync.aligned.m16n8k16.row.col.f32.bf16.bf16.f32 "
        "{%0,%1,%2,%3}, {%4,%5,%6,%7}, {%8,%9}, {%0,%1,%2,%3};"
        : "+f"(d[0]), "+f"(d[1]), "+f"(d[2]), "+f"(d[3])
        : "r"(a[0]), "r"(a[1]), "r"(a[2]), "r"(a[3]), "r"(b0), "r"(b1));
}
__device__ __forceinline__ uint32_t pack_hi(float a, float b) {
    __nv_bfloat162 h = __halves2bfloat162(__float2bfloat16_rn(a), __float2bfloat16_rn(b));
    return *(uint32_t*)&h;
}
__device__ __forceinline__ uint32_t pack_resid(float a, float b) {
    float ha = __bfloat162float(__float2bfloat16_rn(a));
    float hb = __bfloat162float(__float2bfloat16_rn(b));
    return pack_hi(a - ha, b - hb);
}

// ---------------------------------------------------------------------------
// Kernel: head-average of bias_table -> g_bias[257]
// ---------------------------------------------------------------------------
__global__ void bias_avg_kernel(const float* __restrict__ bt) {
    int i = threadIdx.x;
    if (i < 2 * MAXREL + 1) {
        float s = 0.f;
#pragma unroll
        for (int h = 0; h < Hn; h++) s += bt[i * Hn + h];
        g_bias[i] = s * (1.0f / Hn);
    }
}

// ---------------------------------------------------------------------------
// Kernel: fp32 -> bf16 hi/lo split
// ---------------------------------------------------------------------------
__global__ void split_bf16_kernel(const float* __restrict__ in,
                                  __nv_bfloat16* __restrict__ hi,
                                  __nv_bfloat16* __restrict__ lo, int n4) {
    int i = blockIdx.x * blockDim.x + threadIdx.x;
    if (i < n4) {
        float4 v = ((const float4*)in)[i];
        __nv_bfloat16 h0 = __float2bfloat16_rn(v.x);
        __nv_bfloat16 h1 = __float2bfloat16_rn(v.y);
        __nv_bfloat16 h2 = __float2bfloat16_rn(v.z);
        __nv_bfloat16 h3 = __float2bfloat16_rn(v.w);
        __nv_bfloat16 l0 = __float2bfloat16_rn(v.x - __bfloat162float(h0));
        __nv_bfloat16 l1 = __float2bfloat16_rn(v.y - __bfloat162float(h1));
        __nv_bfloat16 l2 = __float2bfloat16_rn(v.z - __bfloat162float(h2));
        __nv_bfloat16 l3 = __float2bfloat16_rn(v.w - __bfloat162float(h3));
        __nv_bfloat162* H = (__nv_bfloat162*)(hi + 4 * (size_t)i);
        __nv_bfloat162* L = (__nv_bfloat162*)(lo + 4 * (size_t)i);
        H[0] = __halves2bfloat162(h0, h1);
        H[1] = __halves2bfloat162(h2, h3);
        L[0] = __halves2bfloat162(l0, l1);
        L[1] = __halves2bfloat162(l2, l3);
    }
}

// ---------------------------------------------------------------------------
// Kernel: mma.sync bf16x3 GEMM  C = A @ W^T + bias  (unchanged, proven)
// ---------------------------------------------------------------------------
#define BM 128
#define BN 128
#define BKC 32
#define NCHUNK (Dn / BKC)            // 24
#define LDE 40
#define GT_TILE_B (128 * LDE * 2)     // 10240

__global__ __launch_bounds__(256) void gemm_mma(
    const __nv_bfloat16* __restrict__ Ah, const __nv_bfloat16* __restrict__ Al,
    const __nv_bfloat16* __restrict__ Bh, const __nv_bfloat16* __restrict__ Bl,
    const float* __restrict__ bias, float* __restrict__ Cf,
    __nv_bfloat16* __restrict__ Ch, __nv_bfloat16* __restrict__ Cl)
{
    __shared__ __align__(16) char sm[4 * GT_TILE_B];
    const int t    = threadIdx.x;
    const int lane = t & 31;
    const int w    = t >> 5;
    const int wm   = w & 3;
    const int wn   = w >> 2;
    const int n0   = blockIdx.x * BN;
    const int m0   = blockIdx.y * BM;
    const uint32_t sbase = smem_u32(sm);

    float acc[2][8][4];
#pragma unroll
    for (int i = 0; i < 2; i++)
#pragma unroll
        for (int j = 0; j < 8; j++)
#pragma unroll
            for (int q = 0; q < 4; q++) acc[i][j][q] = 0.f;

    const int srow  = t >> 1;
    const int shalf = t & 1;
    const __nv_bfloat16* gsrc[4];
    gsrc[0] = Ah + (size_t)(m0 + srow) * Dn + shalf * 16;
    gsrc[1] = Al + (size_t)(m0 + srow) * Dn + shalf * 16;
    gsrc[2] = Bh + (size_t)(n0 + srow) * Dn + shalf * 16;
    gsrc[3] = Bl + (size_t)(n0 + srow) * Dn + shalf * 16;
    const int soff = srow * (LDE * 2) + shalf * 32;

    uint4 v[4][2];
#pragma unroll
    for (int u = 0; u < 4; u++) {
        v[u][0] = *(const uint4*)(gsrc[u]);
        v[u][1] = *(const uint4*)(gsrc[u] + 8);
    }

    for (int c = 0; c < NCHUNK; c++) {
#pragma unroll
        for (int u = 0; u < 4; u++) {
            *(uint4*)(sm + u * GT_TILE_B + soff)      = v[u][0];
            *(uint4*)(sm + u * GT_TILE_B + soff + 16) = v[u][1];
        }
        __syncthreads();

        if (c + 1 < NCHUNK) {
            const int koff = (c + 1) * BKC;
#pragma unroll
            for (int u = 0; u < 4; u++) {
                v[u][0] = *(const uint4*)(gsrc[u] + koff);
                v[u][1] = *(const uint4*)(gsrc[u] + koff + 8);
            }
        }

        const uint32_t sA  = sbase;
        const uint32_t sAl = sbase + GT_TILE_B;
        const uint32_t sB  = sbase + 2 * GT_TILE_B;
        const uint32_t sBl = sbase + 3 * GT_TILE_B;
#pragma unroll
        for (int kk = 0; kk < 2; kk++) {
            uint32_t ah[2][4], al[2][4];
            const uint32_t arow = wm * 32 + (lane & 15);
            const uint32_t acol = (kk * 16 + (lane >> 4) * 8) * 2;
#pragma unroll
            for (int mi = 0; mi < 2; mi++) {
                ldmx4(ah[mi], sA  + (arow + mi * 16) * (LDE * 2) + acol);
                ldmx4(al[mi], sAl + (arow + mi * 16) * (LDE * 2) + acol);
            }
            const uint32_t g     = lane >> 3;
            const uint32_t brow0 = wn * 64 + (g >> 1) * 8 + (lane & 7);
            const uint32_t bcol  = (kk * 16 + (g & 1) * 8) * 2;
#pragma unroll
            for (int np = 0; np < 4; np++) {
                uint32_t bh[4], bl[4];
                ldmx4(bh, sB  + (brow0 + np * 16) * (LDE * 2) + bcol);
                ldmx4(bl, sBl + (brow0 + np * 16) * (LDE * 2) + bcol);
#pragma unroll
                for (int sub = 0; sub < 2; sub++) {
                    const int nt = np * 2 + sub;
                    uint32_t bh0 = bh[sub * 2], bh1 = bh[sub * 2 + 1];
                    uint32_t bl0 = bl[sub * 2], bl1 = bl[sub * 2 + 1];
#pragma unroll
                    for (int mi = 0; mi < 2; mi++) {
                        mma_bf16(acc[mi][nt], ah[mi], bh0, bh1);
                        mma_bf16(acc[mi][nt], al[mi], bh0, bh1);
                        mma_bf16(acc[mi][nt], ah[mi], bl0, bl1);
                    }
                }
            }
        }
        __syncthreads();
    }

    const int colq = 2 * (lane & 3);
#pragma unroll
    for (int nt = 0; nt < 8; nt++) {
        const int colg = n0 + wn * 64 + nt * 8 + colq;
        const float2 bv = *(const float2*)(bias + colg);
#pragma unroll
        for (int mi = 0; mi < 2; mi++) {
            const int r0 = m0 + wm * 32 + mi * 16 + (lane >> 2);
            float x0 = acc[mi][nt][0] + bv.x;
            float x1 = acc[mi][nt][1] + bv.y;
            float x2 = acc[mi][nt][2] + bv.x;
            float x3 = acc[mi][nt][3] + bv.y;
            if (Cf) {
                *(float2*)(Cf + (size_t)r0 * Dn + colg) = make_float2(x0, x1);
                *(float2*)(Cf + (size_t)(r0 + 8) * Dn + colg) = make_float2(x2, x3);
            } else {
                float h0 = __bfloat162float(__float2bfloat16_rn(x0));
                float h1 = __bfloat162float(__float2bfloat16_rn(x1));
                float h2 = __bfloat162float(__float2bfloat16_rn(x2));
                float h3 = __bfloat162float(__float2bfloat16_rn(x3));
                *(uint32_t*)(Ch + (size_t)r0 * Dn + colg)       = pack_hi(x0, x1);
                *(uint32_t*)(Cl + (size_t)r0 * Dn + colg)       = pack_hi(x0 - h0, x1 - h1);
                *(uint32_t*)(Ch + (size_t)(r0 + 8) * Dn + colg) = pack_hi(x2, x3);
                *(uint32_t*)(Cl + (size_t)(r0 + 8) * Dn + colg) = pack_hi(x2 - h2, x3 - h3);
            }
        }
    }
}

// ---------------------------------------------------------------------------
// Kernel: flash attention, tensor cores, bf16x3; P register-resident (FA2).
// Block: 128 q-rows x (head, batch). 8 warps; warp = 16 q-rows.
// Smem: K/V hi/lo (36KB) + Q hi/lo (36KB) + bias -> ~75KB, 2 CTAs/SM.
// ---------------------------------------------------------------------------
#define ROWB 144                       // smem row pitch bytes (72 bf16)
#define SKH  0
#define SKL  (SKH + 64 * ROWB)         // 9216
#define SVH  (SKL + 64 * ROWB)         // 18432
#define SVL  (SVH + 64 * ROWB)         // 27648
#define SQH  (SVL + 64 * ROWB)         // 36864
#define SQL  (SQH + 128 * ROWB)        // 55296
#define SBIAS (SQL + 128 * ROWB)       // 73728
#define ATT_SMEM (SBIAS + 257 * 4 + 12)  // 74768

__global__ __launch_bounds__(256, 2) void attn_mma(
    const __nv_bfloat16* __restrict__ Qh, const __nv_bfloat16* __restrict__ Ql,
    const __nv_bfloat16* __restrict__ Kh, const __nv_bfloat16* __restrict__ Kl,
    const __nv_bfloat16* __restrict__ Vh, const __nv_bfloat16* __restrict__ Vl,
    __nv_bfloat16* __restrict__ Ch, __nv_bfloat16* __restrict__ Cl)
{
    extern __shared__ __align__(16) char sm[];
    const uint32_t sb = smem_u32(sm);
    float* Bsm = (float*)(sm + SBIAS);

    const int t    = threadIdx.x;
    const int lane = t & 31;
    const int wm   = t >> 5;
    const int q0   = blockIdx.x * 128;
    const int h    = blockIdx.y;
    const int b    = blockIdx.z;

    for (int i = t; i < 257; i += 256) Bsm[i] = g_bias[i];

    // stage Q (128 rows x 64 bf16, hi+lo)
#pragma unroll
    for (int u = 0; u < 8; u++) {
        int idx = u * 256 + t;
        int hl  = idx >> 10;
        int r   = (idx >> 3) & 127;
        int c   = idx & 7;
        const __nv_bfloat16* src = (hl ? Ql : Qh)
            + (size_t)(b * Tn + q0 + r) * Dn + h * HDn + c * 8;
        *(uint4*)(sm + (hl ? SQL : SQH) + r * ROWB + c * 16) = *(const uint4*)src;
    }
    __syncthreads();

    // hoist Q fragments: 4 ksteps x (hi,lo)
    uint32_t qf_h[4][4], qf_l[4][4];
    {
        const uint32_t arow = wm * 16 + (lane & 15);
        const uint32_t acolb = (lane >> 4) * 16;
#pragma unroll
        for (int ks = 0; ks < 4; ks++) {
            ldmx4(qf_h[ks], sb + SQH + arow * ROWB + ks * 32 + acolb);
            ldmx4(qf_l[ks], sb + SQL + arow * ROWB + ks * 32 + acolb);
        }
    }

    float m_i[2] = {-1e30f, -1e30f};
    float l_i[2] = {0.f, 0.f};
    float acc[8][4];
#pragma unroll
    for (int dt = 0; dt < 8; dt++)
#pragma unroll
        for (int q = 0; q < 4; q++) acc[dt][q] = 0.f;

    const float scale = 0.125f;
    const int rA = lane >> 2;

    for (int kt = 0; kt < Tn; kt += 64) {
        __syncthreads();   // previous iter's K/V reads done before overwrite
#pragma unroll
        for (int u = 0; u < 8; u++) {
            int idx = u * 256 + t;
            int kv  = idx >> 10;
            int hl  = (idx >> 9) & 1;
            int r   = (idx >> 3) & 63;
            int c   = idx & 7;
            const __nv_bfloat16* src =
                (kv ? (hl ? Vl : Vh) : (hl ? Kl : Kh))
                + (size_t)(b * Tn + kt + r) * Dn + h * HDn + c * 8;
            int dof = kv ? (hl ? SVL : SVH) : (hl ? SKL : SKH);
            *(uint4*)(sm + dof + r * ROWB + c * 16) = *(const uint4*)src;
        }
        __syncthreads();

        // ---- S = Q K^T (3-pass split) ----
        float s[8][4];
#pragma unroll
        for (int nt = 0; nt < 8; nt++)
#pragma unroll
            for (int q = 0; q < 4; q++) s[nt][q] = 0.f;

        const uint32_t g     = lane >> 3;
        const uint32_t brow  = (g >> 1) * 8 + (lane & 7);
        const uint32_t bcolb = (g & 1) * 16;
#pragma unroll
        for (int np = 0; np < 4; np++) {
#pragma unroll
            for (int ks = 0; ks < 4; ks++) {
                uint32_t kh[4], kl[4];
                ldmx4(kh, sb + SKH + (np * 16 + brow) * ROWB + ks * 32 + bcolb);
                ldmx4(kl, sb + SKL + (np * 16 + brow) * ROWB + ks * 32 + bcolb);
#pragma unroll
                for (int sub = 0; sub < 2; sub++) {
                    const int nt = np * 2 + sub;
                    mma_bf16(s[nt], qf_h[ks], kh[sub * 2], kh[sub * 2 + 1]);
                    mma_bf16(s[nt], qf_l[ks], kh[sub * 2], kh[sub * 2 + 1]);
                    mma_bf16(s[nt], qf_h[ks], kl[sub * 2], kl[sub * 2 + 1]);
                }
            }
        }

        // ---- scale + bias + online softmax (values stay in s[][]) ----
        float mrow[2] = {-1e30f, -1e30f};
#pragma unroll
        for (int nt = 0; nt < 8; nt++) {
#pragma unroll
            for (int ri = 0; ri < 2; ri++) {
                const int qi = q0 + wm * 16 + rA + ri * 8;
#pragma unroll
                for (int j = 0; j < 2; j++) {
                    const int kj = kt + nt * 8 + 2 * (lane & 3) + j;
                    int rel = qi - kj;
                    rel = min(max(rel, -MAXREL), MAXREL) + MAXREL;
                    float v = s[nt][2 * ri + j] * scale + Bsm[rel];
                    s[nt][2 * ri + j] = v;
                    mrow[ri] = fmaxf(mrow[ri], v);
                }
            }
        }
#pragma unroll
        for (int ri = 0; ri < 2; ri++) {
            mrow[ri] = fmaxf(mrow[ri], __shfl_xor_sync(0xffffffffu, mrow[ri], 1));
            mrow[ri] = fmaxf(mrow[ri], __shfl_xor_sync(0xffffffffu, mrow[ri], 2));
        }
        float m_new[2], corr[2], rsum[2];
#pragma unroll
        for (int ri = 0; ri < 2; ri++) {
            m_new[ri] = fmaxf(m_i[ri], mrow[ri]);
            corr[ri]  = __expf(m_i[ri] - m_new[ri]);
            rsum[ri]  = 0.f;
        }
        // exp in place; P stays in registers
#pragma unroll
        for (int nt = 0; nt < 8; nt++) {
#pragma unroll
            for (int ri = 0; ri < 2; ri++) {
                float p0 = __expf(s[nt][2 * ri + 0] - m_new[ri]);
                float p1 = __expf(s[nt][2 * ri + 1] - m_new[ri]);
                s[nt][2 * ri + 0] = p0;
                s[nt][2 * ri + 1] = p1;
                rsum[ri] += p0 + p1;
            }
        }
#pragma unroll
        for (int ri = 0; ri < 2; ri++) {
            rsum[ri] += __shfl_xor_sync(0xffffffffu, rsum[ri], 1);
            rsum[ri] += __shfl_xor_sync(0xffffffffu, rsum[ri], 2);
            l_i[ri] = l_i[ri] * corr[ri] + rsum[ri];
            m_i[ri] = m_new[ri];
        }
#pragma unroll
        for (int dt = 0; dt < 8; dt++) {
            acc[dt][0] *= corr[0]; acc[dt][1] *= corr[0];
            acc[dt][2] *= corr[1]; acc[dt][3] *= corr[1];
        }

        // ---- O += P V; P A-fragments built from S C-fragments in registers ----
        const uint32_t vrow  = (lane & 7) + 8 * ((lane >> 3) & 1);
        const uint32_t vcolb = (lane >> 4) * 16;
#pragma unroll
        for (int ks = 0; ks < 4; ks++) {
            // A-fragment (k=16 covering S cols 16ks..16ks+15):
            // a0 = S[2ks](r, 2c:2c+1), a1 = S[2ks](r+8, ..), a2/a3 from S[2ks+1]
            uint32_t ph[4], pl[4];
            ph[0] = pack_hi(s[2 * ks][0],     s[2 * ks][1]);
            ph[1] = pack_hi(s[2 * ks][2],     s[2 * ks][3]);
            ph[2] = pack_hi(s[2 * ks + 1][0], s[2 * ks + 1][1]);
            ph[3] = pack_hi(s[2 * ks + 1][2], s[2 * ks + 1][3]);
            pl[0] = pack_resid(s[2 * ks][0],     s[2 * ks][1]);
            pl[1] = pack_resid(s[2 * ks][2],     s[2 * ks][3]);
            pl[2] = pack_resid(s[2 * ks + 1][0], s[2 * ks + 1][1]);
            pl[3] = pack_resid(s[2 * ks + 1][2], s[2 * ks + 1][3]);
#pragma unroll
            for (int np = 0; np < 4; np++) {
                uint32_t vh[4], vl[4];
                ldmx4t(vh, sb + SVH + (ks * 16 + vrow) * ROWB + np * 32 + vcolb);
                ldmx4t(vl, sb + SVL + (ks * 16 + vrow) * ROWB + np * 32 + vcolb);
#pragma unroll
                for (int sub = 0; sub < 2; sub++) {
                    const int dt = np * 2 + sub;
                    mma_bf16(acc[dt], ph, vh[sub * 2], vh[sub * 2 + 1]);
                    mma_bf16(acc[dt], pl, vh[sub * 2], vh[sub * 2 + 1]);
                    mma_bf16(acc[dt], ph, vl[sub * 2], vl[sub * 2 + 1]);
                }
            }
        }
    }

    // epilogue: normalize, write ctx as bf16 hi/lo
    float inv[2] = {1.0f / l_i[0], 1.0f / l_i[1]};
#pragma unroll
    for (int dt = 0; dt < 8; dt++) {
#pragma unroll
        for (int ri = 0; ri < 2; ri++) {
            float o0 = acc[dt][2 * ri + 0] * inv[ri];
            float o1 = acc[dt][2 * ri + 1] * inv[ri];
            float h0 = __bfloat162float(__float2bfloat16_rn(o0));
            float h1 = __bfloat162float(__float2bfloat16_rn(o1));
            const size_t row = (size_t)(b * Tn + q0 + wm * 16 + rA + ri * 8);
            const int col = h * HDn + dt * 8 + 2 * (lane & 3);
            *(uint32_t*)(Ch + row * Dn + col) = pack_hi(o0, o1);
            *(uint32_t*)(Cl + row * Dn + col) = pack_hi(o0 - h0, o1 - h1);
        }
    }
}

// ---------------------------------------------------------------------------
// Host launcher
// ---------------------------------------------------------------------------
extern "C" void kernel_launch(void* const* d_in, const int* in_sizes, int n_in,
                              void* d_out, int out_size)
{
    const float* x   = (const float*)d_in[0];
    const float* w_q = (const float*)d_in[1];
    const float* b_q = (const float*)d_in[2];
    const float* w_k = (const float*)d_in[3];
    const float* b_k = (const float*)d_in[4];
    const float* w_v = (const float*)d_in[5];
    const float* b_v = (const float*)d_in[6];
    const float* w_o = (const float*)d_in[7];
    const float* b_o = (const float*)d_in[8];
    const float* bt  = (const float*)d_in[9];
    float* out = (float*)d_out;

    __nv_bfloat16 *xh, *xl, *qh, *ql, *kh, *kl, *vh, *vl, *ch, *cl, *wh, *wl;
    cudaGetSymbolAddress((void**)&xh, g_xh);
    cudaGetSymbolAddress((void**)&xl, g_xl);
    cudaGetSymbolAddress((void**)&qh, g_qh);
    cudaGetSymbolAddress((void**)&ql, g_ql);
    cudaGetSymbolAddress((void**)&kh, g_kh);
    cudaGetSymbolAddress((void**)&kl, g_kl);
    cudaGetSymbolAddress((void**)&vh, g_vh);
    cudaGetSymbolAddress((void**)&vl, g_vl);
    cudaGetSymbolAddress((void**)&ch, g_ch);
    cudaGetSymbolAddress((void**)&cl, g_cl);
    cudaGetSymbolAddress((void**)&wh, g_wh);
    cudaGetSymbolAddress((void**)&wl, g_wl);

    cudaFuncSetAttribute(attn_mma,
                         cudaFuncAttributeMaxDynamicSharedMemorySize, ATT_SMEM);

    bias_avg_kernel<<<1, 288>>>(bt);

    const int n4x = Mrows * Dn / 4;
    const int n4w = Dn * Dn / 4;
    split_bf16_kernel<<<(n4x + 255) / 256, 256>>>(x, xh, xl, n4x);
    split_bf16_kernel<<<(n4w + 255) / 256, 256>>>(w_q, wh + 0 * (size_t)Dn * Dn, wl + 0 * (size_t)Dn * Dn, n4w);
    split_bf16_kernel<<<(n4w + 255) / 256, 256>>>(w_k, wh + 1 * (size_t)Dn * Dn, wl + 1 * (size_t)Dn * Dn, n4w);
    split_bf16_kernel<<<(n4w + 255) / 256, 256>>>(w_v, wh + 2 * (size_t)Dn * Dn, wl + 2 * (size_t)Dn * Dn, n4w);
    split_bf16_kernel<<<(n4w + 255) / 256, 256>>>(w_o, wh + 3 * (size_t)Dn * Dn, wl + 3 * (size_t)Dn * Dn, n4w);

    dim3 ggrid(Dn / BN, Mrows / BM);      // (6, 64)
    gemm_mma<<<ggrid, 256>>>(xh, xl, wh + 0 * (size_t)Dn * Dn, wl + 0 * (size_t)Dn * Dn, b_q, nullptr, qh, ql);
    gemm_mma<<<ggrid, 256>>>(xh, xl, wh + 1 * (size_t)Dn * Dn, wl + 1 * (size_t)Dn * Dn, b_k, nullptr, kh, kl);
    gemm_mma<<<ggrid, 256>>>(xh, xl, wh + 2 * (size_t)Dn * Dn, wl + 2 * (size_t)Dn * Dn, b_v, nullptr, vh, vl);

    dim3 agrid(Tn / 128, Hn, Bn);         // (16, 12, 4)
    attn_mma<<<agrid, 256, ATT_SMEM>>>(qh, ql, kh, kl, vh, vl, ch, cl);

    gemm_mma<<<ggrid, 256>>>(ch, cl, wh + 3 * (size_t)Dn * Dn, wl + 3 * (size_t)Dn * Dn, b_o, out, nullptr, nullptr);
}

// round 8
// speedup vs baseline: 2.7375x; 1.0750x over previous
#include <cuda_runtime.h>
#include <cuda_bf16.h>
#include <cstdint>

// Problem constants
#define Bn      4
#define Tn      2048
#define Dn      768
#define Hn      12
#define HDn     64
#define MAXREL  128
#define Mrows   (Bn * Tn)   // 8192

// ---------------------------------------------------------------------------
// Scratch (alloc-free: __device__ globals)
// ---------------------------------------------------------------------------
__device__ float g_bias[2 * MAXREL + 1];

__device__ __align__(16) __nv_bfloat16 g_xh[Mrows * Dn];
__device__ __align__(16) __nv_bfloat16 g_xl[Mrows * Dn];
__device__ __align__(16) __nv_bfloat16 g_qh[Mrows * Dn];
__device__ __align__(16) __nv_bfloat16 g_ql[Mrows * Dn];
__device__ __align__(16) __nv_bfloat16 g_kh[Mrows * Dn];
__device__ __align__(16) __nv_bfloat16 g_kl[Mrows * Dn];
__device__ __align__(16) __nv_bfloat16 g_vh[Mrows * Dn];
__device__ __align__(16) __nv_bfloat16 g_vl[Mrows * Dn];
__device__ __align__(16) __nv_bfloat16 g_ch[Mrows * Dn];
__device__ __align__(16) __nv_bfloat16 g_cl[Mrows * Dn];
__device__ __align__(16) __nv_bfloat16 g_wh[4][Dn * Dn];
__device__ __align__(16) __nv_bfloat16 g_wl[4][Dn * Dn];

// ---------------------------------------------------------------------------
// Helpers
// ---------------------------------------------------------------------------
__device__ __forceinline__ uint32_t smem_u32(const void* p) {
    uint32_t a;
    asm("{ .reg .u64 t; cvta.to.shared.u64 t, %1; cvt.u32.u64 %0, t; }"
        : "=r"(a) : "l"(p));
    return a;
}
__device__ __forceinline__ void ldmx4(uint32_t* r, uint32_t addr) {
    asm volatile("ldmatrix.sync.aligned.m8n8.x4.shared.b16 {%0,%1,%2,%3}, [%4];"
        : "=r"(r[0]), "=r"(r[1]), "=r"(r[2]), "=r"(r[3]) : "r"(addr));
}
__device__ __forceinline__ void ldmx4t(uint32_t* r, uint32_t addr) {
    asm volatile("ldmatrix.sync.aligned.m8n8.x4.trans.shared.b16 {%0,%1,%2,%3}, [%4];"
        : "=r"(r[0]), "=r"(r[1]), "=r"(r[2]), "=r"(r[3]) : "r"(addr));
}
__device__ __forceinline__ void mma_bf16(float* d, const uint32_t* a,
                                         uint32_t b0, uint32_t b1) {
    asm volatile("mma.sync.aligned.m16n8k16.row.col.f32.bf16.bf16.f32 "
        "{%0,%1,%2,%3}, {%4,%5,%6,%7}, {%8,%9}, {%0,%1,%2,%3};"
        : "+f"(d[0]), "+f"(d[1]), "+f"(d[2]), "+f"(d[3])
        : "r"(a[0]), "r"(a[1]), "r"(a[2]), "r"(a[3]), "r"(b0), "r"(b1));
}
__device__ __forceinline__ uint32_t pack_hi(float a, float b) {
    __nv_bfloat162 h = __halves2bfloat162(__float2bfloat16_rn(a), __float2bfloat16_rn(b));
    return *(uint32_t*)&h;
}
__device__ __forceinline__ uint32_t pack_resid(float a, float b) {
    float ha = __bfloat162float(__float2bfloat16_rn(a));
    float hb = __bfloat162float(__float2bfloat16_rn(b));
    return pack_hi(a - ha, b - hb);
}
#define CP_ASYNC16(dst, src) \
    asm volatile("cp.async.cg.shared.global [%0], [%1], 16;" :: "r"(dst), "l"(src))
#define CP_COMMIT() asm volatile("cp.async.commit_group;")
#define CP_WAIT0()  asm volatile("cp.async.wait_group 0;")

// ---------------------------------------------------------------------------
// Kernel: head-average of bias_table -> g_bias[257]
// ---------------------------------------------------------------------------
__global__ void bias_avg_kernel(const float* __restrict__ bt) {
    int i = threadIdx.x;
    if (i < 2 * MAXREL + 1) {
        float s = 0.f;
#pragma unroll
        for (int h = 0; h < Hn; h++) s += bt[i * Hn + h];
        g_bias[i] = s * (1.0f / Hn);
    }
}

// ---------------------------------------------------------------------------
// Kernel: fp32 -> bf16 hi/lo split
// ---------------------------------------------------------------------------
__global__ void split_bf16_kernel(const float* __restrict__ in,
                                  __nv_bfloat16* __restrict__ hi,
                                  __nv_bfloat16* __restrict__ lo, int n4) {
    int i = blockIdx.x * blockDim.x + threadIdx.x;
    if (i < n4) {
        float4 v = ((const float4*)in)[i];
        __nv_bfloat16 h0 = __float2bfloat16_rn(v.x);
        __nv_bfloat16 h1 = __float2bfloat16_rn(v.y);
        __nv_bfloat16 h2 = __float2bfloat16_rn(v.z);
        __nv_bfloat16 h3 = __float2bfloat16_rn(v.w);
        __nv_bfloat16 l0 = __float2bfloat16_rn(v.x - __bfloat162float(h0));
        __nv_bfloat16 l1 = __float2bfloat16_rn(v.y - __bfloat162float(h1));
        __nv_bfloat16 l2 = __float2bfloat16_rn(v.z - __bfloat162float(h2));
        __nv_bfloat16 l3 = __float2bfloat16_rn(v.w - __bfloat162float(h3));
        __nv_bfloat162* H = (__nv_bfloat162*)(hi + 4 * (size_t)i);
        __nv_bfloat162* L = (__nv_bfloat162*)(lo + 4 * (size_t)i);
        H[0] = __halves2bfloat162(h0, h1);
        H[1] = __halves2bfloat162(h2, h3);
        L[0] = __halves2bfloat162(l0, l1);
        L[1] = __halves2bfloat162(l2, l3);
    }
}

// ---------------------------------------------------------------------------
// GEMM core (bf16x3 mma.sync), shared by QKV-fused and O-proj kernels.
// Block tile 128x128x32; 8 warps (4M x 2N); warp tile 32x64.
// ---------------------------------------------------------------------------
#define BM 128
#define BN 128
#define BKC 32
#define NCHUNK (Dn / BKC)            // 24
#define LDE 40
#define GT_TILE_B (128 * LDE * 2)     // 10240

struct GemmOut {
    float acc[2][8][4];
};

__device__ __forceinline__ void gemm_core(
    const __nv_bfloat16* __restrict__ Ah, const __nv_bfloat16* __restrict__ Al,
    const __nv_bfloat16* __restrict__ Bh, const __nv_bfloat16* __restrict__ Bl,
    int m0, int n0, char* sm, GemmOut& out)
{
    const int t    = threadIdx.x;
    const int lane = t & 31;
    const int w    = t >> 5;
    const int wm   = w & 3;
    const int wn   = w >> 2;
    const uint32_t sbase = smem_u32(sm);

#pragma unroll
    for (int i = 0; i < 2; i++)
#pragma unroll
        for (int j = 0; j < 8; j++)
#pragma unroll
            for (int q = 0; q < 4; q++) out.acc[i][j][q] = 0.f;

    const int srow  = t >> 1;
    const int shalf = t & 1;
    const __nv_bfloat16* gsrc[4];
    gsrc[0] = Ah + (size_t)(m0 + srow) * Dn + shalf * 16;
    gsrc[1] = Al + (size_t)(m0 + srow) * Dn + shalf * 16;
    gsrc[2] = Bh + (size_t)(n0 + srow) * Dn + shalf * 16;
    gsrc[3] = Bl + (size_t)(n0 + srow) * Dn + shalf * 16;
    const int soff = srow * (LDE * 2) + shalf * 32;

    uint4 v[4][2];
#pragma unroll
    for (int u = 0; u < 4; u++) {
        v[u][0] = *(const uint4*)(gsrc[u]);
        v[u][1] = *(const uint4*)(gsrc[u] + 8);
    }

    for (int c = 0; c < NCHUNK; c++) {
#pragma unroll
        for (int u = 0; u < 4; u++) {
            *(uint4*)(sm + u * GT_TILE_B + soff)      = v[u][0];
            *(uint4*)(sm + u * GT_TILE_B + soff + 16) = v[u][1];
        }
        __syncthreads();

        if (c + 1 < NCHUNK) {
            const int koff = (c + 1) * BKC;
#pragma unroll
            for (int u = 0; u < 4; u++) {
                v[u][0] = *(const uint4*)(gsrc[u] + koff);
                v[u][1] = *(const uint4*)(gsrc[u] + koff + 8);
            }
        }

        const uint32_t sA  = sbase;
        const uint32_t sAl = sbase + GT_TILE_B;
        const uint32_t sB  = sbase + 2 * GT_TILE_B;
        const uint32_t sBl = sbase + 3 * GT_TILE_B;
#pragma unroll
        for (int kk = 0; kk < 2; kk++) {
            uint32_t ah[2][4], al[2][4];
            const uint32_t arow = wm * 32 + (lane & 15);
            const uint32_t acol = (kk * 16 + (lane >> 4) * 8) * 2;
#pragma unroll
            for (int mi = 0; mi < 2; mi++) {
                ldmx4(ah[mi], sA  + (arow + mi * 16) * (LDE * 2) + acol);
                ldmx4(al[mi], sAl + (arow + mi * 16) * (LDE * 2) + acol);
            }
            const uint32_t g     = lane >> 3;
            const uint32_t brow0 = wn * 64 + (g >> 1) * 8 + (lane & 7);
            const uint32_t bcol  = (kk * 16 + (g & 1) * 8) * 2;
#pragma unroll
            for (int np = 0; np < 4; np++) {
                uint32_t bh[4], bl[4];
                ldmx4(bh, sB  + (brow0 + np * 16) * (LDE * 2) + bcol);
                ldmx4(bl, sBl + (brow0 + np * 16) * (LDE * 2) + bcol);
#pragma unroll
                for (int sub = 0; sub < 2; sub++) {
                    const int nt = np * 2 + sub;
                    uint32_t bh0 = bh[sub * 2], bh1 = bh[sub * 2 + 1];
                    uint32_t bl0 = bl[sub * 2], bl1 = bl[sub * 2 + 1];
#pragma unroll
                    for (int mi = 0; mi < 2; mi++) {
                        mma_bf16(out.acc[mi][nt], ah[mi], bh0, bh1);
                        mma_bf16(out.acc[mi][nt], al[mi], bh0, bh1);
                        mma_bf16(out.acc[mi][nt], ah[mi], bl0, bl1);
                    }
                }
            }
        }
        __syncthreads();
    }
}

// ---------------------------------------------------------------------------
// Kernel: fused QKV projection. grid (18, 64): x -> (weight, n-block).
// Output routed to q/k/v hi+lo.
// ---------------------------------------------------------------------------
__global__ __launch_bounds__(256) void gemm_qkv(
    const __nv_bfloat16* __restrict__ Xh, const __nv_bfloat16* __restrict__ Xl,
    const __nv_bfloat16* __restrict__ Wh, const __nv_bfloat16* __restrict__ Wl,
    const float* __restrict__ bq, const float* __restrict__ bk,
    const float* __restrict__ bv,
    __nv_bfloat16* __restrict__ Qh, __nv_bfloat16* __restrict__ Ql,
    __nv_bfloat16* __restrict__ Kh, __nv_bfloat16* __restrict__ Kl,
    __nv_bfloat16* __restrict__ Vh, __nv_bfloat16* __restrict__ Vl)
{
    __shared__ __align__(16) char sm[4 * GT_TILE_B];
    const int nb    = blockIdx.x;
    const int which = nb / 6;            // 0=Q 1=K 2=V
    const int n0    = (nb - which * 6) * BN;
    const int m0    = blockIdx.y * BM;

    const __nv_bfloat16* Bh = Wh + (size_t)which * Dn * Dn;
    const __nv_bfloat16* Bl = Wl + (size_t)which * Dn * Dn;
    const float* bias = (which == 0) ? bq : (which == 1) ? bk : bv;
    __nv_bfloat16* Ch = (which == 0) ? Qh : (which == 1) ? Kh : Vh;
    __nv_bfloat16* Cl = (which == 0) ? Ql : (which == 1) ? Kl : Vl;

    GemmOut o;
    gemm_core(Xh, Xl, Bh, Bl, m0, n0, sm, o);

    const int lane = threadIdx.x & 31;
    const int w    = threadIdx.x >> 5;
    const int wm   = w & 3;
    const int wn   = w >> 2;
    const int colq = 2 * (lane & 3);
#pragma unroll
    for (int nt = 0; nt < 8; nt++) {
        const int colg = n0 + wn * 64 + nt * 8 + colq;
        const float2 bv2 = *(const float2*)(bias + colg);
#pragma unroll
        for (int mi = 0; mi < 2; mi++) {
            const int r0 = m0 + wm * 32 + mi * 16 + (lane >> 2);
            float x0 = o.acc[mi][nt][0] + bv2.x;
            float x1 = o.acc[mi][nt][1] + bv2.y;
            float x2 = o.acc[mi][nt][2] + bv2.x;
            float x3 = o.acc[mi][nt][3] + bv2.y;
            *(uint32_t*)(Ch + (size_t)r0 * Dn + colg)       = pack_hi(x0, x1);
            *(uint32_t*)(Cl + (size_t)r0 * Dn + colg)       = pack_resid(x0, x1);
            *(uint32_t*)(Ch + (size_t)(r0 + 8) * Dn + colg) = pack_hi(x2, x3);
            *(uint32_t*)(Cl + (size_t)(r0 + 8) * Dn + colg) = pack_resid(x2, x3);
        }
    }
}

// ---------------------------------------------------------------------------
// Kernel: output projection (fp32 out). grid (6, 64).
// ---------------------------------------------------------------------------
__global__ __launch_bounds__(256) void gemm_oproj(
    const __nv_bfloat16* __restrict__ Ah, const __nv_bfloat16* __restrict__ Al,
    const __nv_bfloat16* __restrict__ Bh, const __nv_bfloat16* __restrict__ Bl,
    const float* __restrict__ bias, float* __restrict__ Cf)
{
    __shared__ __align__(16) char sm[4 * GT_TILE_B];
    const int n0 = blockIdx.x * BN;
    const int m0 = blockIdx.y * BM;

    GemmOut o;
    gemm_core(Ah, Al, Bh, Bl, m0, n0, sm, o);

    const int lane = threadIdx.x & 31;
    const int w    = threadIdx.x >> 5;
    const int wm   = w & 3;
    const int wn   = w >> 2;
    const int colq = 2 * (lane & 3);
#pragma unroll
    for (int nt = 0; nt < 8; nt++) {
        const int colg = n0 + wn * 64 + nt * 8 + colq;
        const float2 bv2 = *(const float2*)(bias + colg);
#pragma unroll
        for (int mi = 0; mi < 2; mi++) {
            const int r0 = m0 + wm * 32 + mi * 16 + (lane >> 2);
            *(float2*)(Cf + (size_t)r0 * Dn + colg) =
                make_float2(o.acc[mi][nt][0] + bv2.x, o.acc[mi][nt][1] + bv2.y);
            *(float2*)(Cf + (size_t)(r0 + 8) * Dn + colg) =
                make_float2(o.acc[mi][nt][2] + bv2.x, o.acc[mi][nt][3] + bv2.y);
        }
    }
}

// ---------------------------------------------------------------------------
// Kernel: flash attention; P register-resident; cp.async double-buffered K/V.
// ---------------------------------------------------------------------------
#define ROWB 144                       // smem row pitch bytes
// per-stage KV layout (offsets within stage):
#define OKH  0
#define OKL  (64 * ROWB)               // 9216
#define OVH  (2 * 64 * ROWB)           // 18432
#define OVL  (3 * 64 * ROWB)           // 27648
#define KV_STAGE_B (4 * 64 * ROWB)     // 36864
#define SQH  (2 * KV_STAGE_B)          // 73728
#define SQL  (SQH + 128 * ROWB)        // 92160
#define SBIAS (SQL + 128 * ROWB)       // 110592
#define ATT_SMEM (SBIAS + 257 * 4 + 12)  // 111632

__global__ __launch_bounds__(256, 2) void attn_mma(
    const __nv_bfloat16* __restrict__ Qh, const __nv_bfloat16* __restrict__ Ql,
    const __nv_bfloat16* __restrict__ Kh, const __nv_bfloat16* __restrict__ Kl,
    const __nv_bfloat16* __restrict__ Vh, const __nv_bfloat16* __restrict__ Vl,
    __nv_bfloat16* __restrict__ Ch, __nv_bfloat16* __restrict__ Cl)
{
    extern __shared__ __align__(16) char sm[];
    const uint32_t sb = smem_u32(sm);
    float* Bsm = (float*)(sm + SBIAS);

    const int t    = threadIdx.x;
    const int lane = t & 31;
    const int wm   = t >> 5;
    const int q0   = blockIdx.x * 128;
    const int h    = blockIdx.y;
    const int b    = blockIdx.z;

    for (int i = t; i < 257; i += 256) Bsm[i] = g_bias[i];

    // issue Q stage (cp.async)
#pragma unroll
    for (int u = 0; u < 8; u++) {
        int idx = u * 256 + t;
        int hl  = idx >> 10;
        int r   = (idx >> 3) & 127;
        int c   = idx & 7;
        const __nv_bfloat16* src = (hl ? Ql : Qh)
            + (size_t)(b * Tn + q0 + r) * Dn + h * HDn + c * 8;
        CP_ASYNC16(sb + (hl ? SQL : SQH) + r * ROWB + c * 16, src);
    }
    // issue K/V tile 0 into stage 0
#pragma unroll
    for (int u = 0; u < 8; u++) {
        int idx = u * 256 + t;
        int kv  = idx >> 10;
        int hl  = (idx >> 9) & 1;
        int r   = (idx >> 3) & 63;
        int c   = idx & 7;
        const __nv_bfloat16* src =
            (kv ? (hl ? Vl : Vh) : (hl ? Kl : Kh))
            + (size_t)(b * Tn + r) * Dn + h * HDn + c * 8;
        uint32_t dst = sb + (kv ? (hl ? OVL : OVH) : (hl ? OKL : OKH)) + r * ROWB + c * 16;
        CP_ASYNC16(dst, src);
    }
    CP_COMMIT();
    CP_WAIT0();
    __syncthreads();

    // hoist Q fragments
    uint32_t qf_h[4][4], qf_l[4][4];
    {
        const uint32_t arow = wm * 16 + (lane & 15);
        const uint32_t acolb = (lane >> 4) * 16;
#pragma unroll
        for (int ks = 0; ks < 4; ks++) {
            ldmx4(qf_h[ks], sb + SQH + arow * ROWB + ks * 32 + acolb);
            ldmx4(qf_l[ks], sb + SQL + arow * ROWB + ks * 32 + acolb);
        }
    }

    float m_i[2] = {-1e30f, -1e30f};
    float l_i[2] = {0.f, 0.f};
    float acc[8][4];
#pragma unroll
    for (int dt = 0; dt < 8; dt++)
#pragma unroll
        for (int q = 0; q < 4; q++) acc[dt][q] = 0.f;

    const float scale = 0.125f;
    const int rA = lane >> 2;
    const int NITER = Tn / 64;     // 32

    for (int it = 0; it < NITER; it++) {
        const int kt = it * 64;
        const uint32_t cur = sb + (it & 1) * KV_STAGE_B;

        // prefetch next K/V tile into other stage
        if (it + 1 < NITER) {
            const uint32_t nxt = sb + ((it + 1) & 1) * KV_STAGE_B;
            const int ktn = kt + 64;
#pragma unroll
            for (int u = 0; u < 8; u++) {
                int idx = u * 256 + t;
                int kv  = idx >> 10;
                int hl  = (idx >> 9) & 1;
                int r   = (idx >> 3) & 63;
                int c   = idx & 7;
                const __nv_bfloat16* src =
                    (kv ? (hl ? Vl : Vh) : (hl ? Kl : Kh))
                    + (size_t)(b * Tn + ktn + r) * Dn + h * HDn + c * 8;
                uint32_t dst = nxt + (kv ? (hl ? OVL : OVH) : (hl ? OKL : OKH)) + r * ROWB + c * 16;
                CP_ASYNC16(dst, src);
            }
            CP_COMMIT();
        }

        // ---- S = Q K^T (3-pass split) from stage `cur` ----
        float s[8][4];
#pragma unroll
        for (int nt = 0; nt < 8; nt++)
#pragma unroll
            for (int q = 0; q < 4; q++) s[nt][q] = 0.f;

        const uint32_t g     = lane >> 3;
        const uint32_t brow  = (g >> 1) * 8 + (lane & 7);
        const uint32_t bcolb = (g & 1) * 16;
#pragma unroll
        for (int np = 0; np < 4; np++) {
#pragma unroll
            for (int ks = 0; ks < 4; ks++) {
                uint32_t kh[4], kl[4];
                ldmx4(kh, cur + OKH + (np * 16 + brow) * ROWB + ks * 32 + bcolb);
                ldmx4(kl, cur + OKL + (np * 16 + brow) * ROWB + ks * 32 + bcolb);
#pragma unroll
                for (int sub = 0; sub < 2; sub++) {
                    const int nt = np * 2 + sub;
                    mma_bf16(s[nt], qf_h[ks], kh[sub * 2], kh[sub * 2 + 1]);
                    mma_bf16(s[nt], qf_l[ks], kh[sub * 2], kh[sub * 2 + 1]);
                    mma_bf16(s[nt], qf_h[ks], kl[sub * 2], kl[sub * 2 + 1]);
                }
            }
        }

        // ---- scale + bias + online softmax ----
        float mrow[2] = {-1e30f, -1e30f};
#pragma unroll
        for (int nt = 0; nt < 8; nt++) {
#pragma unroll
            for (int ri = 0; ri < 2; ri++) {
                const int qi = q0 + wm * 16 + rA + ri * 8;
#pragma unroll
                for (int j = 0; j < 2; j++) {
                    const int kj = kt + nt * 8 + 2 * (lane & 3) + j;
                    int rel = qi - kj;
                    rel = min(max(rel, -MAXREL), MAXREL) + MAXREL;
                    float v = s[nt][2 * ri + j] * scale + Bsm[rel];
                    s[nt][2 * ri + j] = v;
                    mrow[ri] = fmaxf(mrow[ri], v);
                }
            }
        }
#pragma unroll
        for (int ri = 0; ri < 2; ri++) {
            mrow[ri] = fmaxf(mrow[ri], __shfl_xor_sync(0xffffffffu, mrow[ri], 1));
            mrow[ri] = fmaxf(mrow[ri], __shfl_xor_sync(0xffffffffu, mrow[ri], 2));
        }
        float m_new[2], corr[2], rsum[2];
#pragma unroll
        for (int ri = 0; ri < 2; ri++) {
            m_new[ri] = fmaxf(m_i[ri], mrow[ri]);
            corr[ri]  = __expf(m_i[ri] - m_new[ri]);
            rsum[ri]  = 0.f;
        }
#pragma unroll
        for (int nt = 0; nt < 8; nt++) {
#pragma unroll
            for (int ri = 0; ri < 2; ri++) {
                float p0 = __expf(s[nt][2 * ri + 0] - m_new[ri]);
                float p1 = __expf(s[nt][2 * ri + 1] - m_new[ri]);
                s[nt][2 * ri + 0] = p0;
                s[nt][2 * ri + 1] = p1;
                rsum[ri] += p0 + p1;
            }
        }
#pragma unroll
        for (int ri = 0; ri < 2; ri++) {
            rsum[ri] += __shfl_xor_sync(0xffffffffu, rsum[ri], 1);
            rsum[ri] += __shfl_xor_sync(0xffffffffu, rsum[ri], 2);
            l_i[ri] = l_i[ri] * corr[ri] + rsum[ri];
            m_i[ri] = m_new[ri];
        }
#pragma unroll
        for (int dt = 0; dt < 8; dt++) {
            acc[dt][0] *= corr[0]; acc[dt][1] *= corr[0];
            acc[dt][2] *= corr[1]; acc[dt][3] *= corr[1];
        }

        // ---- O += P V (P from registers; V via ldmatrix.trans) ----
        const uint32_t vrow  = (lane & 7) + 8 * ((lane >> 3) & 1);
        const uint32_t vcolb = (lane >> 4) * 16;
#pragma unroll
        for (int ks = 0; ks < 4; ks++) {
            uint32_t ph[4], pl[4];
            ph[0] = pack_hi(s[2 * ks][0],     s[2 * ks][1]);
            ph[1] = pack_hi(s[2 * ks][2],     s[2 * ks][3]);
            ph[2] = pack_hi(s[2 * ks + 1][0], s[2 * ks + 1][1]);
            ph[3] = pack_hi(s[2 * ks + 1][2], s[2 * ks + 1][3]);
            pl[0] = pack_resid(s[2 * ks][0],     s[2 * ks][1]);
            pl[1] = pack_resid(s[2 * ks][2],     s[2 * ks][3]);
            pl[2] = pack_resid(s[2 * ks + 1][0], s[2 * ks + 1][1]);
            pl[3] = pack_resid(s[2 * ks + 1][2], s[2 * ks + 1][3]);
#pragma unroll
            for (int np = 0; np < 4; np++) {
                uint32_t vh[4], vl[4];
                ldmx4t(vh, cur + OVH + (ks * 16 + vrow) * ROWB + np * 32 + vcolb);
                ldmx4t(vl, cur + OVL + (ks * 16 + vrow) * ROWB + np * 32 + vcolb);
#pragma unroll
                for (int sub = 0; sub < 2; sub++) {
                    const int dt = np * 2 + sub;
                    mma_bf16(acc[dt], ph, vh[sub * 2], vh[sub * 2 + 1]);
                    mma_bf16(acc[dt], pl, vh[sub * 2], vh[sub * 2 + 1]);
                    mma_bf16(acc[dt], ph, vl[sub * 2], vl[sub * 2 + 1]);
                }
            }
        }

        // next stage ready?
        CP_WAIT0();
        __syncthreads();
    }

    // epilogue: normalize, write ctx as bf16 hi/lo
    float inv[2] = {1.0f / l_i[0], 1.0f / l_i[1]};
#pragma unroll
    for (int dt = 0; dt < 8; dt++) {
#pragma unroll
        for (int ri = 0; ri < 2; ri++) {
            float o0 = acc[dt][2 * ri + 0] * inv[ri];
            float o1 = acc[dt][2 * ri + 1] * inv[ri];
            const size_t row = (size_t)(b * Tn + q0 + wm * 16 + rA + ri * 8);
            const int col = h * HDn + dt * 8 + 2 * (lane & 3);
            *(uint32_t*)(Ch + row * Dn + col) = pack_hi(o0, o1);
            *(uint32_t*)(Cl + row * Dn + col) = pack_resid(o0, o1);
        }
    }
}

// ---------------------------------------------------------------------------
// Host launcher
// ---------------------------------------------------------------------------
extern "C" void kernel_launch(void* const* d_in, const int* in_sizes, int n_in,
                              void* d_out, int out_size)
{
    const float* x   = (const float*)d_in[0];
    const float* w_q = (const float*)d_in[1];
    const float* b_q = (const float*)d_in[2];
    const float* w_k = (const float*)d_in[3];
    const float* b_k = (const float*)d_in[4];
    const float* w_v = (const float*)d_in[5];
    const float* b_v = (const float*)d_in[6];
    const float* w_o = (const float*)d_in[7];
    const float* b_o = (const float*)d_in[8];
    const float* bt  = (const float*)d_in[9];
    float* out = (float*)d_out;

    __nv_bfloat16 *xh, *xl, *qh, *ql, *kh, *kl, *vh, *vl, *ch, *cl, *wh, *wl;
    cudaGetSymbolAddress((void**)&xh, g_xh);
    cudaGetSymbolAddress((void**)&xl, g_xl);
    cudaGetSymbolAddress((void**)&qh, g_qh);
    cudaGetSymbolAddress((void**)&ql, g_ql);
    cudaGetSymbolAddress((void**)&kh, g_kh);
    cudaGetSymbolAddress((void**)&kl, g_kl);
    cudaGetSymbolAddress((void**)&vh, g_vh);
    cudaGetSymbolAddress((void**)&vl, g_vl);
    cudaGetSymbolAddress((void**)&ch, g_ch);
    cudaGetSymbolAddress((void**)&cl, g_cl);
    cudaGetSymbolAddress((void**)&wh, g_wh);
    cudaGetSymbolAddress((void**)&wl, g_wl);

    cudaFuncSetAttribute(attn_mma,
                         cudaFuncAttributeMaxDynamicSharedMemorySize, ATT_SMEM);

    bias_avg_kernel<<<1, 288>>>(bt);

    const int n4x = Mrows * Dn / 4;
    const int n4w = Dn * Dn / 4;
    split_bf16_kernel<<<(n4x + 255) / 256, 256>>>(x, xh, xl, n4x);
    split_bf16_kernel<<<(n4w + 255) / 256, 256>>>(w_q, wh + 0 * (size_t)Dn * Dn, wl + 0 * (size_t)Dn * Dn, n4w);
    split_bf16_kernel<<<(n4w + 255) / 256, 256>>>(w_k, wh + 1 * (size_t)Dn * Dn, wl + 1 * (size_t)Dn * Dn, n4w);
    split_bf16_kernel<<<(n4w + 255) / 256, 256>>>(w_v, wh + 2 * (size_t)Dn * Dn, wl + 2 * (size_t)Dn * Dn, n4w);
    split_bf16_kernel<<<(n4w + 255) / 256, 256>>>(w_o, wh + 3 * (size_t)Dn * Dn, wl + 3 * (size_t)Dn * Dn, n4w);

    // fused QKV projection: grid (18, 64)
    dim3 qgrid(3 * Dn / BN, Mrows / BM);
    gemm_qkv<<<qgrid, 256>>>(xh, xl, wh, wl, b_q, b_k, b_v,
                             qh, ql, kh, kl, vh, vl);

    dim3 agrid(Tn / 128, Hn, Bn);         // (16, 12, 4)
    attn_mma<<<agrid, 256, ATT_SMEM>>>(qh, ql, kh, kl, vh, vl, ch, cl);

    dim3 ogrid(Dn / BN, Mrows / BM);      // (6, 64)
    gemm_oproj<<<ogrid, 256>>>(ch, cl, wh + 3 * (size_t)Dn * Dn, wl + 3 * (size_t)Dn * Dn, b_o, out);
}